// round 5
// baseline (speedup 1.0000x reference)
#include <cuda_runtime.h>
#include <cuda_bf16.h>
#include <cstdint>

#define T_  1024
#define H_  2048
#define I_  1408
#define E_  16
#define C_  512
#define TK_ 2048

// ---------------- scratch (device globals) ---------------------------------
__device__ int   g_topi[TK_];
__device__ float g_topw[TK_];
__device__ int   g_slot_tok[E_ * C_];
__device__ int   g_slot_of_j[TK_];
__device__ int   g_cnt[E_];
__device__ __align__(16) __nv_bfloat16 g_xb_hi[(size_t)E_ * C_ * H_];
__device__ __align__(16) __nv_bfloat16 g_xb_lo[(size_t)E_ * C_ * H_];
__device__ __align__(16) __nv_bfloat16 g_act_hi[(size_t)E_ * C_ * I_];
__device__ __align__(16) __nv_bfloat16 g_act_lo[(size_t)E_ * C_ * I_];
__device__ float g_ybuf[(size_t)E_ * C_ * H_];

// ---------------- helpers ----------------------------------------------------
__device__ __forceinline__ uint32_t smem_u32(const void* p) {
    return (uint32_t)__cvta_generic_to_shared(p);
}
static __device__ __forceinline__ void ldsm_x4(uint32_t addr, uint32_t r[4]) {
    asm volatile("ldmatrix.sync.aligned.m8n8.x4.shared.b16 {%0,%1,%2,%3},[%4];"
                 : "=r"(r[0]), "=r"(r[1]), "=r"(r[2]), "=r"(r[3]) : "r"(addr));
}
static __device__ __forceinline__ void mma16816(float d[4], const uint32_t a[4],
                                                uint32_t b0, uint32_t b1) {
    asm volatile(
        "mma.sync.aligned.m16n8k16.row.col.f32.bf16.bf16.f32 "
        "{%0,%1,%2,%3},{%4,%5,%6,%7},{%8,%9},{%0,%1,%2,%3};"
        : "+f"(d[0]), "+f"(d[1]), "+f"(d[2]), "+f"(d[3])
        : "r"(a[0]), "r"(a[1]), "r"(a[2]), "r"(a[3]), "r"(b0), "r"(b1));
}
static __device__ __forceinline__ void split2(float f0, float f1, uint32_t& hi, uint32_t& lo) {
    __nv_bfloat16 h0 = __float2bfloat16_rn(f0);
    __nv_bfloat16 h1 = __float2bfloat16_rn(f1);
    __nv_bfloat16 l0 = __float2bfloat16_rn(f0 - __bfloat162float(h0));
    __nv_bfloat16 l1 = __float2bfloat16_rn(f1 - __bfloat162float(h1));
    hi = ((uint32_t)__bfloat16_as_ushort(h1) << 16) | __bfloat16_as_ushort(h0);
    lo = ((uint32_t)__bfloat16_as_ushort(l1) << 16) | __bfloat16_as_ushort(l0);
}
static __device__ __forceinline__ void cp16(uint32_t dst, const void* src) {
    asm volatile("cp.async.ca.shared.global [%0],[%1],16;" ::"r"(dst), "l"(src));
}
static __device__ __forceinline__ void cp_commit() {
    asm volatile("cp.async.commit_group;" ::: "memory");
}
static __device__ __forceinline__ void cp_wait0() {
    asm volatile("cp.async.wait_group 0;" ::: "memory");
}
static __device__ __forceinline__ void mbar_init(uint32_t a, uint32_t cnt) {
    asm volatile("mbarrier.init.shared.b64 [%0], %1;" ::"r"(a), "r"(cnt) : "memory");
}
static __device__ __forceinline__ void mbar_arrive(uint32_t a) {
    asm volatile("mbarrier.arrive.shared.b64 _, [%0];" ::"r"(a) : "memory");
}
static __device__ __forceinline__ void mbar_wait(uint32_t a, uint32_t parity) {
    uint32_t done = 0;
    while (!done) {
        asm volatile(
            "{\n\t.reg .pred p;\n\t"
            "mbarrier.try_wait.parity.acquire.cta.shared::cta.b64 p, [%1], %2, 0x989680;\n\t"
            "selp.b32 %0,1,0,p;\n\t}"
            : "=r"(done) : "r"(a), "r"(parity) : "memory");
    }
}

// SMEM tile geometry: rows padded to 80B (64B data + 16B) -> conflict-free LDSM
#define ROWB      80
#define PLANE_SZ  (128 * ROWB)          // 10240
#define STAGE_SZ  (4 * PLANE_SZ)        // 40960: A_hi, A_lo, B_hi, B_lo
#define A_HI 0
#define A_LO PLANE_SZ
#define B_HI (2 * PLANE_SZ)
#define B_LO (3 * PLANE_SZ)
#define NSTAGE 4
#define BAR_OFF (NSTAGE * STAGE_SZ)     // 163840
#define SMEM_TOTAL (BAR_OFF + 128)

// ---------------- routing ---------------------------------------------------
__global__ void router_kernel(const float* __restrict__ logits) {
    int tid = threadIdx.x;
    for (int t = tid; t < T_; t += 512) {
        const float* l = logits + t * E_;
        float v[E_];
#pragma unroll
        for (int e = 0; e < E_; e++) v[e] = l[e];
        int i1 = 0; float m1 = v[0];
#pragma unroll
        for (int e = 1; e < E_; e++) if (v[e] > m1) { m1 = v[e]; i1 = e; }
        int i2 = -1; float m2 = -1e30f;
#pragma unroll
        for (int e = 0; e < E_; e++) if (e != i1 && v[e] > m2) { m2 = v[e]; i2 = e; }
        float w0 = 1.f / (1.f + __expf(m2 - m1));
        g_topi[2 * t] = i1; g_topi[2 * t + 1] = i2;
        g_topw[2 * t] = w0; g_topw[2 * t + 1] = 1.f - w0;
    }
    __syncthreads();
    int wid = tid >> 5, lane = tid & 31;
    if (wid < E_) {
        int e = wid, base = 0;
        for (int j0 = 0; j0 < TK_; j0 += 32) {
            int j = j0 + lane;
            int rid = g_topi[j];
            unsigned m = __ballot_sync(0xffffffffu, rid == e);
            if (rid == e) {
                int p = base + __popc(m & ((1u << lane) - 1u));
                if (p < C_) {
                    g_slot_tok[e * C_ + p] = j >> 1;
                    g_slot_of_j[j] = e * C_ + p;
                } else g_slot_of_j[j] = -1;
            }
            base += __popc(m);
        }
        if (lane == 0) g_cnt[e] = base < C_ ? base : C_;
    }
}

// ---------------- prepass: gather x rows, split into bf16 hi/lo -------------
__global__ __launch_bounds__(256) void prepass_kernel(const float* __restrict__ x) {
    int e = blockIdx.x >> 2, row0 = (blockIdx.x & 3) << 7;
    int cnt = g_cnt[e];
    if (row0 >= cnt) return;
    int k0 = blockIdx.y * (H_ / 4);   // 512-col slab
    int wid = threadIdx.x >> 5, lane = threadIdx.x & 31;
    for (int r = row0 + wid; r < row0 + 128; r += 8) {
        bool v = r < cnt;
        const float* src = v ? x + (size_t)g_slot_tok[e * C_ + r] * H_ : nullptr;
        size_t dst = (size_t)(e * C_ + r) * H_;
        for (int k = k0 + lane * 4; k < k0 + H_ / 4; k += 128) {
            float4 f = v ? *(const float4*)(src + k) : make_float4(0, 0, 0, 0);
            uint32_t h0, l0, h1, l1;
            split2(f.x, f.y, h0, l0);
            split2(f.z, f.w, h1, l1);
            *(uint2*)(g_xb_hi + dst + k) = make_uint2(h0, h1);
            *(uint2*)(g_xb_lo + dst + k) = make_uint2(l0, l1);
        }
    }
}

// ---------------- consumer mma over one smem stage ---------------------------
// Product-major MMA order: same accumulator re-touched at distance 4, breaking
// the 3-deep RAW chains that capped tensor-pipe activity at ~47%.
static __device__ __forceinline__ void mma_stage(uint32_t sst, int mbase, int nbase,
                                                 int lane, float acc[2][8][4]) {
    int a_row = lane & 15, a_kh = lane >> 4;
    int b_mat = lane >> 3, b_r = lane & 7;
    int b_radd = (b_mat & 2) ? 8 : 0, b_kh = b_mat & 1;
#pragma unroll
    for (int k16 = 0; k16 < 2; k16++) {
        uint32_t ah[2][4], al[2][4];
#pragma unroll
        for (int mt = 0; mt < 2; mt++) {
            uint32_t ao = (mbase + mt * 16 + a_row) * ROWB + k16 * 32 + a_kh * 16;
            ldsm_x4(sst + A_HI + ao, ah[mt]);
            ldsm_x4(sst + A_LO + ao, al[mt]);
        }
#pragma unroll
        for (int pj = 0; pj < 4; pj++) {
            uint32_t bh[4], bl[4];
            uint32_t bo = (nbase + pj * 16 + b_radd + b_r) * ROWB + k16 * 32 + b_kh * 16;
            ldsm_x4(sst + B_HI + bo, bh);
            ldsm_x4(sst + B_LO + bo, bl);
            int n0t = 2 * pj, n1t = 2 * pj + 1;
            // hh product across 4 independent accumulators
            mma16816(acc[0][n0t], ah[0], bh[0], bh[1]);
            mma16816(acc[1][n0t], ah[1], bh[0], bh[1]);
            mma16816(acc[0][n1t], ah[0], bh[2], bh[3]);
            mma16816(acc[1][n1t], ah[1], bh[2], bh[3]);
            // hl product
            mma16816(acc[0][n0t], ah[0], bl[0], bl[1]);
            mma16816(acc[1][n0t], ah[1], bl[0], bl[1]);
            mma16816(acc[0][n1t], ah[0], bl[2], bl[3]);
            mma16816(acc[1][n1t], ah[1], bl[2], bl[3]);
            // lh product
            mma16816(acc[0][n0t], al[0], bh[0], bh[1]);
            mma16816(acc[1][n0t], al[1], bh[0], bh[1]);
            mma16816(acc[0][n1t], al[0], bh[2], bh[3]);
            mma16816(acc[1][n1t], al[1], bh[2], bh[3]);
        }
    }
}

// ---------------- warp-specialized GEMM body (shared by both GEMMs) ----------
template <typename F>
static __device__ __forceinline__ void gemm_ws(uint32_t sb, int NCH, int Kdim,
                                               const __nv_bfloat16* ahi,
                                               const __nv_bfloat16* alo, F rowptr,
                                               float acc[2][8][4]) {
    const int tid = threadIdx.x;
    if (tid == 0) {
#pragma unroll
        for (int s = 0; s < NSTAGE; s++) {
            mbar_init(sb + BAR_OFF + s * 8, 128);        // full: producers arrive
            mbar_init(sb + BAR_OFF + 64 + s * 8, 256);   // empty: consumers arrive
        }
    }
    __syncthreads();

    if (tid < 256) {
        // ---- consumer ----
        const int lane = tid & 31, wid = tid >> 5;
        const int mbase = (wid & 3) * 32, nbase = (wid >> 2) * 64;
        for (int c = 0; c < NCH; c++) {
            int s = c & (NSTAGE - 1), r = c >> 2;
            mbar_wait(sb + BAR_OFF + s * 8, r & 1);
            mma_stage(sb + s * STAGE_SZ, mbase, nbase, lane, acc);
            mbar_arrive(sb + BAR_OFF + 64 + s * 8);
        }
    } else {
        // ---- producer ----
        const int ptid = tid - 256;
        const float* rp = rowptr(ptid);
        float4 breg[8];
#pragma unroll
        for (int q = 0; q < 8; q++) breg[q] = *(const float4*)(rp + q * 4);
        for (int c = 0; c < NCH; c++) {
            int s = c & (NSTAGE - 1), r = c >> 2;
            if (r > 0) mbar_wait(sb + BAR_OFF + 64 + s * 8, (r - 1) & 1);
            uint32_t sst = sb + s * STAGE_SZ;
            // A planes via cp.async: 1024 x 16B granules
#pragma unroll
            for (int j = 0; j < 8; j++) {
                int g = ptid + 128 * j;
                int plane = g >> 9, rem = g & 511, row = rem >> 2, seg = rem & 3;
                const __nv_bfloat16* src =
                    (plane ? alo : ahi) + (size_t)row * Kdim + c * 32 + seg * 8;
                cp16(sst + (plane ? A_LO : A_HI) + row * ROWB + seg * 16, src);
            }
            cp_commit();
            // B: convert this chunk's prefetched regs
            uint32_t h[16], l[16];
#pragma unroll
            for (int q = 0; q < 8; q++) {
                split2(breg[q].x, breg[q].y, h[2 * q], l[2 * q]);
                split2(breg[q].z, breg[q].w, h[2 * q + 1], l[2 * q + 1]);
            }
            uint32_t bh = sst + B_HI + ptid * ROWB;
            uint32_t bl = sst + B_LO + ptid * ROWB;
#pragma unroll
            for (int m = 0; m < 4; m++) {
                asm volatile("st.shared.v4.b32 [%0],{%1,%2,%3,%4};" ::"r"(bh + 16 * m),
                             "r"(h[4 * m]), "r"(h[4 * m + 1]), "r"(h[4 * m + 2]),
                             "r"(h[4 * m + 3]));
                asm volatile("st.shared.v4.b32 [%0],{%1,%2,%3,%4};" ::"r"(bl + 16 * m),
                             "r"(l[4 * m]), "r"(l[4 * m + 1]), "r"(l[4 * m + 2]),
                             "r"(l[4 * m + 3]));
            }
            // prefetch next chunk's B
            if (c + 1 < NCH) {
                const float* np = rp + (c + 1) * 32;
#pragma unroll
                for (int q = 0; q < 8; q++) breg[q] = *(const float4*)(np + q * 4);
            }
            cp_wait0();
            mbar_arrive(sb + BAR_OFF + s * 8);
        }
    }
}

// ---------------- GEMM1: xbuf @ w13^T (gate/up interleaved), SiLU -> act -----
__global__ __launch_bounds__(384, 1) void gemm1_mma(const float* __restrict__ w13) {
    extern __shared__ char smem[];
    const int e = blockIdx.y >> 2;
    const int row0 = (blockIdx.y & 3) << 7;
    const int cnt = g_cnt[e];
    if (row0 >= cnt) return;
    const int n0 = blockIdx.x << 6;   // 64 I-cols
    uint32_t sb = smem_u32(smem);

    const __nv_bfloat16* ahi = g_xb_hi + (size_t)(e * C_ + row0) * H_;
    const __nv_bfloat16* alo = g_xb_lo + (size_t)(e * C_ + row0) * H_;
    const float* wbase = w13 + (size_t)e * 2 * I_ * H_;
    auto rowptr = [&](int rb) {
        int grow = (rb & 1) ? (I_ + n0 + (rb >> 1)) : (n0 + (rb >> 1));
        return wbase + (size_t)grow * H_;
    };

    float acc[2][8][4];
#pragma unroll
    for (int a = 0; a < 2; a++)
#pragma unroll
        for (int b = 0; b < 8; b++)
#pragma unroll
            for (int c = 0; c < 4; c++) acc[a][b][c] = 0.f;

    gemm_ws(sb, H_ / 32, H_, ahi, alo, rowptr, acc);

    const int tid = threadIdx.x;
    if (tid < 256) {
        const int lane = tid & 31, wid = tid >> 5;
        const int mbase = (wid & 3) * 32, nbase = (wid >> 2) * 64;
#pragma unroll
        for (int mt = 0; mt < 2; mt++) {
#pragma unroll
            for (int half = 0; half < 2; half++) {
                int r = row0 + mbase + mt * 16 + (lane >> 2) + half * 8;
                if (r < cnt) {
                    size_t ob = (size_t)(e * C_ + r) * I_;
#pragma unroll
                    for (int nt = 0; nt < 8; nt++) {
                        int cn = nbase + nt * 8 + (lane & 3) * 2;
                        int icol = n0 + (cn >> 1);
                        float g = acc[mt][nt][2 * half];
                        float u = acc[mt][nt][2 * half + 1];
                        float a = g / (1.f + __expf(-g)) * u;
                        __nv_bfloat16 hi = __float2bfloat16_rn(a);
                        __nv_bfloat16 lo = __float2bfloat16_rn(a - __bfloat162float(hi));
                        g_act_hi[ob + icol] = hi;
                        g_act_lo[ob + icol] = lo;
                    }
                }
            }
        }
    }
}

// ---------------- GEMM2: act @ w2^T -> ybuf (fp32) ---------------------------
__global__ __launch_bounds__(384, 1) void gemm2_mma(const float* __restrict__ w2) {
    extern __shared__ char smem[];
    const int e = blockIdx.y >> 2;
    const int row0 = (blockIdx.y & 3) << 7;
    const int cnt = g_cnt[e];
    if (row0 >= cnt) return;
    const int n0 = blockIdx.x << 7;   // 128 H-cols
    uint32_t sb = smem_u32(smem);

    const __nv_bfloat16* ahi = g_act_hi + (size_t)(e * C_ + row0) * I_;
    const __nv_bfloat16* alo = g_act_lo + (size_t)(e * C_ + row0) * I_;
    const float* wbase = w2 + (size_t)e * H_ * I_;
    auto rowptr = [&](int rb) { return wbase + (size_t)(n0 + rb) * I_; };

    float acc[2][8][4];
#pragma unroll
    for (int a = 0; a < 2; a++)
#pragma unroll
        for (int b = 0; b < 8; b++)
#pragma unroll
            for (int c = 0; c < 4; c++) acc[a][b][c] = 0.f;

    gemm_ws(sb, I_ / 32, I_, ahi, alo, rowptr, acc);

    const int tid = threadIdx.x;
    if (tid < 256) {
        const int lane = tid & 31, wid = tid >> 5;
        const int mbase = (wid & 3) * 32, nbase = (wid >> 2) * 64;
#pragma unroll
        for (int mt = 0; mt < 2; mt++) {
#pragma unroll
            for (int half = 0; half < 2; half++) {
                int r = row0 + mbase + mt * 16 + (lane >> 2) + half * 8;
                if (r < cnt) {
                    float* ob = g_ybuf + (size_t)(e * C_ + r) * H_ + n0;
#pragma unroll
                    for (int nt = 0; nt < 8; nt++) {
                        int col = nbase + nt * 8 + (lane & 3) * 2;
                        *(float2*)(ob + col) =
                            make_float2(acc[mt][nt][2 * half], acc[mt][nt][2 * half + 1]);
                    }
                }
            }
        }
    }
}

// ---------------- combine ----------------------------------------------------
__global__ void combine_kernel(float* __restrict__ out) {
    int idx = blockIdx.x * blockDim.x + threadIdx.x;
    if (idx >= T_ * H_ / 4) return;
    int t = idx >> 9;
    int h = (idx & 511) << 2;
    float w0 = g_topw[2 * t], w1 = g_topw[2 * t + 1];
    int s0 = g_slot_of_j[2 * t], s1 = g_slot_of_j[2 * t + 1];
    float4 r = make_float4(0, 0, 0, 0);
    if (s0 >= 0) {
        float4 v = *(const float4*)(g_ybuf + (size_t)s0 * H_ + h);
        r.x += w0 * v.x; r.y += w0 * v.y; r.z += w0 * v.z; r.w += w0 * v.w;
    }
    if (s1 >= 0) {
        float4 v = *(const float4*)(g_ybuf + (size_t)s1 * H_ + h);
        r.x += w1 * v.x; r.y += w1 * v.y; r.z += w1 * v.z; r.w += w1 * v.w;
    }
    *(float4*)(out + (size_t)t * H_ + h) = r;
}

// ---------------- launch ----------------------------------------------------
extern "C" void kernel_launch(void* const* d_in, const int* in_sizes, int n_in,
                              void* d_out, int out_size) {
    const float* x      = (const float*)d_in[0];
    const float* logits = (const float*)d_in[1];
    const float* w13    = (const float*)d_in[2];
    const float* w2     = (const float*)d_in[3];
    float* out          = (float*)d_out;

    static int smem_set = 0;
    if (!smem_set) {
        cudaFuncSetAttribute(gemm1_mma, cudaFuncAttributeMaxDynamicSharedMemorySize, SMEM_TOTAL);
        cudaFuncSetAttribute(gemm2_mma, cudaFuncAttributeMaxDynamicSharedMemorySize, SMEM_TOTAL);
        smem_set = 1;
    }

    router_kernel<<<1, 512>>>(logits);
    prepass_kernel<<<dim3(E_ * (C_ / 128), 4), 256>>>(x);
    gemm1_mma<<<dim3(I_ / 64, E_ * (C_ / 128)), 384, SMEM_TOTAL>>>(w13);
    gemm2_mma<<<dim3(H_ / 128, E_ * (C_ / 128)), 384, SMEM_TOTAL>>>(w2);
    combine_kernel<<<(T_ * H_ / 4 + 255) / 256, 256>>>(out);
}

// round 8
// speedup vs baseline: 1.2552x; 1.2552x over previous
#include <cuda_runtime.h>
#include <cuda_bf16.h>
#include <cstdint>

#define T_  1024
#define H_  2048
#define I_  1408
#define E_  16
#define C_  512
#define TK_ 2048

// ---------------- scratch (device globals) ---------------------------------
__device__ int   g_topi[TK_];
__device__ float g_topw[TK_];
__device__ int   g_slot_tok[E_ * C_];
__device__ int   g_slot_of_j[TK_];
__device__ int   g_cnt[E_];
__device__ __align__(16) __nv_bfloat16 g_xb_hi[(size_t)E_ * C_ * H_];
__device__ __align__(16) __nv_bfloat16 g_xb_lo[(size_t)E_ * C_ * H_];
__device__ __align__(16) __nv_bfloat16 g_act_hi[(size_t)E_ * C_ * I_];
__device__ __align__(16) __nv_bfloat16 g_act_lo[(size_t)E_ * C_ * I_];
__device__ float g_ybuf[(size_t)E_ * C_ * H_];

// ---------------- helpers ----------------------------------------------------
__device__ __forceinline__ uint32_t smem_u32(const void* p) {
    return (uint32_t)__cvta_generic_to_shared(p);
}
static __device__ __forceinline__ void ldsm_x4(uint32_t addr, uint32_t r[4]) {
    asm volatile("ldmatrix.sync.aligned.m8n8.x4.shared.b16 {%0,%1,%2,%3},[%4];"
                 : "=r"(r[0]), "=r"(r[1]), "=r"(r[2]), "=r"(r[3]) : "r"(addr));
}
static __device__ __forceinline__ void mma16816(float d[4], const uint32_t a[4],
                                                uint32_t b0, uint32_t b1) {
    asm volatile(
        "mma.sync.aligned.m16n8k16.row.col.f32.bf16.bf16.f32 "
        "{%0,%1,%2,%3},{%4,%5,%6,%7},{%8,%9},{%0,%1,%2,%3};"
        : "+f"(d[0]), "+f"(d[1]), "+f"(d[2]), "+f"(d[3])
        : "r"(a[0]), "r"(a[1]), "r"(a[2]), "r"(a[3]), "r"(b0), "r"(b1));
}
static __device__ __forceinline__ void split2(float f0, float f1, uint32_t& hi, uint32_t& lo) {
    __nv_bfloat16 h0 = __float2bfloat16_rn(f0);
    __nv_bfloat16 h1 = __float2bfloat16_rn(f1);
    __nv_bfloat16 l0 = __float2bfloat16_rn(f0 - __bfloat162float(h0));
    __nv_bfloat16 l1 = __float2bfloat16_rn(f1 - __bfloat162float(h1));
    hi = ((uint32_t)__bfloat16_as_ushort(h1) << 16) | __bfloat16_as_ushort(h0);
    lo = ((uint32_t)__bfloat16_as_ushort(l1) << 16) | __bfloat16_as_ushort(l0);
}
static __device__ __forceinline__ void cp16(uint32_t dst, const void* src) {
    asm volatile("cp.async.ca.shared.global [%0],[%1],16;" ::"r"(dst), "l"(src));
}
static __device__ __forceinline__ void cp_commit() {
    asm volatile("cp.async.commit_group;" ::: "memory");
}
static __device__ __forceinline__ void cp_wait0() {
    asm volatile("cp.async.wait_group 0;" ::: "memory");
}
static __device__ __forceinline__ void mbar_init(uint32_t a, uint32_t cnt) {
    asm volatile("mbarrier.init.shared.b64 [%0], %1;" ::"r"(a), "r"(cnt) : "memory");
}
static __device__ __forceinline__ void mbar_arrive(uint32_t a) {
    asm volatile("mbarrier.arrive.shared.b64 _, [%0];" ::"r"(a) : "memory");
}
static __device__ __forceinline__ void mbar_wait(uint32_t a, uint32_t parity) {
    uint32_t done = 0;
    while (!done) {
        asm volatile(
            "{\n\t.reg .pred p;\n\t"
            "mbarrier.try_wait.parity.acquire.cta.shared::cta.b64 p, [%1], %2, 0x989680;\n\t"
            "selp.b32 %0,1,0,p;\n\t}"
            : "=r"(done) : "r"(a), "r"(parity) : "memory");
    }
}

// SMEM tile geometry: 64 A-rows x 128 B-rows x 32 K, rows padded to 80B
#define ROWB      80
#define A_ROWS    64
#define B_ROWS    128
#define A_PLANE   (A_ROWS * ROWB)       // 5120
#define B_PLANE   (B_ROWS * ROWB)       // 10240
#define A_HI 0
#define A_LO A_PLANE
#define B_HI (2 * A_PLANE)
#define B_LO (2 * A_PLANE + B_PLANE)
#define STAGE_SZ  (2 * A_PLANE + 2 * B_PLANE)  // 30720
#define NSTAGE 3
#define BAR_OFF (NSTAGE * STAGE_SZ)     // 92160
#define SMEM_TOTAL (BAR_OFF + 128)      // 92288 -> 2 CTAs/SM fit

// ---------------- routing ---------------------------------------------------
__global__ void router_kernel(const float* __restrict__ logits) {
    int tid = threadIdx.x;
    for (int t = tid; t < T_; t += 512) {
        const float* l = logits + t * E_;
        float v[E_];
#pragma unroll
        for (int e = 0; e < E_; e++) v[e] = l[e];
        int i1 = 0; float m1 = v[0];
#pragma unroll
        for (int e = 1; e < E_; e++) if (v[e] > m1) { m1 = v[e]; i1 = e; }
        int i2 = -1; float m2 = -1e30f;
#pragma unroll
        for (int e = 0; e < E_; e++) if (e != i1 && v[e] > m2) { m2 = v[e]; i2 = e; }
        float w0 = 1.f / (1.f + __expf(m2 - m1));
        g_topi[2 * t] = i1; g_topi[2 * t + 1] = i2;
        g_topw[2 * t] = w0; g_topw[2 * t + 1] = 1.f - w0;
    }
    __syncthreads();
    int wid = tid >> 5, lane = tid & 31;
    if (wid < E_) {
        int e = wid, base = 0;
        for (int j0 = 0; j0 < TK_; j0 += 32) {
            int j = j0 + lane;
            int rid = g_topi[j];
            unsigned m = __ballot_sync(0xffffffffu, rid == e);
            if (rid == e) {
                int p = base + __popc(m & ((1u << lane) - 1u));
                if (p < C_) {
                    g_slot_tok[e * C_ + p] = j >> 1;
                    g_slot_of_j[j] = e * C_ + p;
                } else g_slot_of_j[j] = -1;
            }
            base += __popc(m);
        }
        if (lane == 0) g_cnt[e] = base < C_ ? base : C_;
    }
}

// ---------------- prepass: gather x rows, split into bf16 hi/lo -------------
__global__ __launch_bounds__(256) void prepass_kernel(const float* __restrict__ x) {
    int e = blockIdx.x >> 2, row0 = (blockIdx.x & 3) << 7;
    int cnt = g_cnt[e];
    if (row0 >= cnt) return;
    int k0 = blockIdx.y * (H_ / 4);   // 512-col slab
    int wid = threadIdx.x >> 5, lane = threadIdx.x & 31;
    for (int r = row0 + wid; r < row0 + 128; r += 8) {
        bool v = r < cnt;
        const float* src = v ? x + (size_t)g_slot_tok[e * C_ + r] * H_ : nullptr;
        size_t dst = (size_t)(e * C_ + r) * H_;
        for (int k = k0 + lane * 4; k < k0 + H_ / 4; k += 128) {
            float4 f = v ? *(const float4*)(src + k) : make_float4(0, 0, 0, 0);
            uint32_t h0, l0, h1, l1;
            split2(f.x, f.y, h0, l0);
            split2(f.z, f.w, h1, l1);
            *(uint2*)(g_xb_hi + dst + k) = make_uint2(h0, h1);
            *(uint2*)(g_xb_lo + dst + k) = make_uint2(l0, l1);
        }
    }
}

// ---------------- consumer mma over one smem stage (R4 grouped order) --------
// Warp tile: 32 rows x 32 cols. acc[2][4][4].
static __device__ __forceinline__ void mma_stage(uint32_t sst, int mbase, int nbase,
                                                 int lane, float acc[2][4][4]) {
    int a_row = lane & 15, a_kh = lane >> 4;
    int b_mat = lane >> 3, b_r = lane & 7;
    int b_radd = (b_mat & 2) ? 8 : 0, b_kh = b_mat & 1;
#pragma unroll
    for (int k16 = 0; k16 < 2; k16++) {
        uint32_t ah[2][4], al[2][4];
#pragma unroll
        for (int mt = 0; mt < 2; mt++) {
            uint32_t ao = (mbase + mt * 16 + a_row) * ROWB + k16 * 32 + a_kh * 16;
            ldsm_x4(sst + A_HI + ao, ah[mt]);
            ldsm_x4(sst + A_LO + ao, al[mt]);
        }
#pragma unroll
        for (int pj = 0; pj < 2; pj++) {
            uint32_t bh[4], bl[4];
            uint32_t bo = (nbase + pj * 16 + b_radd + b_r) * ROWB + k16 * 32 + b_kh * 16;
            ldsm_x4(sst + B_HI + bo, bh);
            ldsm_x4(sst + B_LO + bo, bl);
#pragma unroll
            for (int t = 0; t < 2; t++) {
                int nt = 2 * pj + t;
#pragma unroll
                for (int mt = 0; mt < 2; mt++) {
                    mma16816(acc[mt][nt], ah[mt], bh[2 * t], bh[2 * t + 1]);
                    mma16816(acc[mt][nt], ah[mt], bl[2 * t], bl[2 * t + 1]);
                    mma16816(acc[mt][nt], al[mt], bh[2 * t], bh[2 * t + 1]);
                }
            }
        }
    }
}

// ---------------- warp-specialized GEMM body ---------------------------------
// 256 consumer threads (8 warps, 2M x 4N, each 32x32) + 128 producer threads.
template <typename F>
static __device__ __forceinline__ void gemm_ws(uint32_t sb, int NCH, int Kdim,
                                               const __nv_bfloat16* ahi,
                                               const __nv_bfloat16* alo, F rowptr,
                                               float acc[2][4][4]) {
    const int tid = threadIdx.x;
    if (tid == 0) {
#pragma unroll
        for (int s = 0; s < NSTAGE; s++) {
            mbar_init(sb + BAR_OFF + s * 8, 128);        // full: producers arrive
            mbar_init(sb + BAR_OFF + 64 + s * 8, 256);   // empty: consumers arrive
        }
    }
    __syncthreads();

    if (tid < 256) {
        // ---- consumer ----
        const int lane = tid & 31, wid = tid >> 5;
        const int mbase = (wid & 1) * 32, nbase = (wid >> 1) * 32;
        int s = 0, ph = 0;
        for (int c = 0; c < NCH; c++) {
            mbar_wait(sb + BAR_OFF + s * 8, ph);
            mma_stage(sb + s * STAGE_SZ, mbase, nbase, lane, acc);
            mbar_arrive(sb + BAR_OFF + 64 + s * 8);
            if (++s == NSTAGE) { s = 0; ph ^= 1; }
        }
    } else {
        // ---- producer ----
        const int ptid = tid - 256;
        const float* rp = rowptr(ptid);
        float4 breg[8];
#pragma unroll
        for (int q = 0; q < 8; q++) breg[q] = *(const float4*)(rp + q * 4);
        int s = 0, ph = 0;
        for (int c = 0; c < NCH; c++) {
            if (c >= NSTAGE) mbar_wait(sb + BAR_OFF + 64 + s * 8, ph ^ 1);
            uint32_t sst = sb + s * STAGE_SZ;
            // A planes via cp.async: 512 x 16B granules (64 rows x 32 k x 2 planes)
#pragma unroll
            for (int j = 0; j < 4; j++) {
                int g = ptid + 128 * j;
                int plane = g >> 8, rem = g & 255, row = rem >> 2, seg = rem & 3;
                const __nv_bfloat16* src =
                    (plane ? alo : ahi) + (size_t)row * Kdim + c * 32 + seg * 8;
                cp16(sst + (plane ? A_LO : A_HI) + row * ROWB + seg * 16, src);
            }
            cp_commit();
            // B: convert this chunk's prefetched regs (one row per producer thread)
            uint32_t h[16], l[16];
#pragma unroll
            for (int q = 0; q < 8; q++) {
                split2(breg[q].x, breg[q].y, h[2 * q], l[2 * q]);
                split2(breg[q].z, breg[q].w, h[2 * q + 1], l[2 * q + 1]);
            }
            uint32_t bh = sst + B_HI + ptid * ROWB;
            uint32_t bl = sst + B_LO + ptid * ROWB;
#pragma unroll
            for (int m = 0; m < 4; m++) {
                asm volatile("st.shared.v4.b32 [%0],{%1,%2,%3,%4};" ::"r"(bh + 16 * m),
                             "r"(h[4 * m]), "r"(h[4 * m + 1]), "r"(h[4 * m + 2]),
                             "r"(h[4 * m + 3]));
                asm volatile("st.shared.v4.b32 [%0],{%1,%2,%3,%4};" ::"r"(bl + 16 * m),
                             "r"(l[4 * m]), "r"(l[4 * m + 1]), "r"(l[4 * m + 2]),
                             "r"(l[4 * m + 3]));
            }
            // prefetch next chunk's B
            if (c + 1 < NCH) {
                const float* np = rp + (c + 1) * 32;
#pragma unroll
                for (int q = 0; q < 8; q++) breg[q] = *(const float4*)(np + q * 4);
            }
            cp_wait0();
            mbar_arrive(sb + BAR_OFF + s * 8);
            if (++s == NSTAGE) { s = 0; ph ^= 1; }
        }
    }
}

// ---------------- GEMM1: xbuf @ w13^T (gate/up interleaved), SiLU -> act -----
__global__ __launch_bounds__(384, 2) void gemm1_mma(const float* __restrict__ w13) {
    extern __shared__ char smem[];
    const int e = blockIdx.y >> 3;
    const int row0 = (blockIdx.y & 7) << 6;   // 64-row tiles
    const int cnt = g_cnt[e];
    if (row0 >= cnt) return;
    const int n0 = blockIdx.x << 6;           // 64 I-cols (128 interleaved B-rows)
    uint32_t sb = smem_u32(smem);

    const __nv_bfloat16* ahi = g_xb_hi + (size_t)(e * C_ + row0) * H_;
    const __nv_bfloat16* alo = g_xb_lo + (size_t)(e * C_ + row0) * H_;
    const float* wbase = w13 + (size_t)e * 2 * I_ * H_;
    auto rowptr = [&](int rb) {
        int grow = (rb & 1) ? (I_ + n0 + (rb >> 1)) : (n0 + (rb >> 1));
        return wbase + (size_t)grow * H_;
    };

    float acc[2][4][4];
#pragma unroll
    for (int a = 0; a < 2; a++)
#pragma unroll
        for (int b = 0; b < 4; b++)
#pragma unroll
            for (int c = 0; c < 4; c++) acc[a][b][c] = 0.f;

    gemm_ws(sb, H_ / 32, H_, ahi, alo, rowptr, acc);

    const int tid = threadIdx.x;
    if (tid < 256) {
        const int lane = tid & 31, wid = tid >> 5;
        const int mbase = (wid & 1) * 32, nbase = (wid >> 1) * 32;
#pragma unroll
        for (int mt = 0; mt < 2; mt++) {
#pragma unroll
            for (int half = 0; half < 2; half++) {
                int r = row0 + mbase + mt * 16 + (lane >> 2) + half * 8;
                if (r < cnt) {
                    size_t ob = (size_t)(e * C_ + r) * I_;
#pragma unroll
                    for (int nt = 0; nt < 4; nt++) {
                        int cn = nbase + nt * 8 + (lane & 3) * 2;
                        int icol = n0 + (cn >> 1);
                        float g = acc[mt][nt][2 * half];
                        float u = acc[mt][nt][2 * half + 1];
                        float a = g / (1.f + __expf(-g)) * u;
                        __nv_bfloat16 hi = __float2bfloat16_rn(a);
                        __nv_bfloat16 lo = __float2bfloat16_rn(a - __bfloat162float(hi));
                        g_act_hi[ob + icol] = hi;
                        g_act_lo[ob + icol] = lo;
                    }
                }
            }
        }
    }
}

// ---------------- GEMM2: act @ w2^T -> ybuf (fp32) ---------------------------
__global__ __launch_bounds__(384, 2) void gemm2_mma(const float* __restrict__ w2) {
    extern __shared__ char smem[];
    const int e = blockIdx.y >> 3;
    const int row0 = (blockIdx.y & 7) << 6;
    const int cnt = g_cnt[e];
    if (row0 >= cnt) return;
    const int n0 = blockIdx.x << 7;   // 128 H-cols
    uint32_t sb = smem_u32(smem);

    const __nv_bfloat16* ahi = g_act_hi + (size_t)(e * C_ + row0) * I_;
    const __nv_bfloat16* alo = g_act_lo + (size_t)(e * C_ + row0) * I_;
    const float* wbase = w2 + (size_t)e * H_ * I_;
    auto rowptr = [&](int rb) { return wbase + (size_t)(n0 + rb) * I_; };

    float acc[2][4][4];
#pragma unroll
    for (int a = 0; a < 2; a++)
#pragma unroll
        for (int b = 0; b < 4; b++)
#pragma unroll
            for (int c = 0; c < 4; c++) acc[a][b][c] = 0.f;

    gemm_ws(sb, I_ / 32, I_, ahi, alo, rowptr, acc);

    const int tid = threadIdx.x;
    if (tid < 256) {
        const int lane = tid & 31, wid = tid >> 5;
        const int mbase = (wid & 1) * 32, nbase = (wid >> 1) * 32;
#pragma unroll
        for (int mt = 0; mt < 2; mt++) {
#pragma unroll
            for (int half = 0; half < 2; half++) {
                int r = row0 + mbase + mt * 16 + (lane >> 2) + half * 8;
                if (r < cnt) {
                    float* ob = g_ybuf + (size_t)(e * C_ + r) * H_ + n0;
#pragma unroll
                    for (int nt = 0; nt < 4; nt++) {
                        int col = nbase + nt * 8 + (lane & 3) * 2;
                        *(float2*)(ob + col) =
                            make_float2(acc[mt][nt][2 * half], acc[mt][nt][2 * half + 1]);
                    }
                }
            }
        }
    }
}

// ---------------- combine ----------------------------------------------------
__global__ void combine_kernel(float* __restrict__ out) {
    int idx = blockIdx.x * blockDim.x + threadIdx.x;
    if (idx >= T_ * H_ / 4) return;
    int t = idx >> 9;
    int h = (idx & 511) << 2;
    float w0 = g_topw[2 * t], w1 = g_topw[2 * t + 1];
    int s0 = g_slot_of_j[2 * t], s1 = g_slot_of_j[2 * t + 1];
    float4 r = make_float4(0, 0, 0, 0);
    if (s0 >= 0) {
        float4 v = *(const float4*)(g_ybuf + (size_t)s0 * H_ + h);
        r.x += w0 * v.x; r.y += w0 * v.y; r.z += w0 * v.z; r.w += w0 * v.w;
    }
    if (s1 >= 0) {
        float4 v = *(const float4*)(g_ybuf + (size_t)s1 * H_ + h);
        r.x += w1 * v.x; r.y += w1 * v.y; r.z += w1 * v.z; r.w += w1 * v.w;
    }
    *(float4*)(out + (size_t)t * H_ + h) = r;
}

// ---------------- launch ----------------------------------------------------
extern "C" void kernel_launch(void* const* d_in, const int* in_sizes, int n_in,
                              void* d_out, int out_size) {
    const float* x      = (const float*)d_in[0];
    const float* logits = (const float*)d_in[1];
    const float* w13    = (const float*)d_in[2];
    const float* w2     = (const float*)d_in[3];
    float* out          = (float*)d_out;

    static int smem_set = 0;
    if (!smem_set) {
        cudaFuncSetAttribute(gemm1_mma, cudaFuncAttributeMaxDynamicSharedMemorySize, SMEM_TOTAL);
        cudaFuncSetAttribute(gemm2_mma, cudaFuncAttributeMaxDynamicSharedMemorySize, SMEM_TOTAL);
        smem_set = 1;
    }

    router_kernel<<<1, 512>>>(logits);
    prepass_kernel<<<dim3(E_ * (C_ / 128), 4), 256>>>(x);
    gemm1_mma<<<dim3(I_ / 64, E_ * (C_ / 64)), 384, SMEM_TOTAL>>>(w13);
    gemm2_mma<<<dim3(H_ / 128, E_ * (C_ / 64)), 384, SMEM_TOTAL>>>(w2);
    combine_kernel<<<(T_ * H_ / 4 + 255) / 256, 256>>>(out);
}

// round 14
// speedup vs baseline: 2.0193x; 1.6088x over previous
#include <cuda_runtime.h>
#include <cuda_fp16.h>
#include <cstdint>

#define T_  1024
#define H_  2048
#define I_  1408
#define E_  16
#define C_  512
#define TK_ 2048

// ---------------- scratch (device globals) ---------------------------------
__device__ int   g_topi[TK_];
__device__ float g_topw[TK_];
__device__ int   g_slot_tok[E_ * C_];
__device__ int   g_slot_of_j[TK_];
__device__ int   g_cnt[E_];
__device__ __align__(16) __half g_xb[(size_t)E_ * C_ * H_];
__device__ __align__(16) __half g_act[(size_t)E_ * C_ * I_];
__device__ float g_ybuf[(size_t)E_ * C_ * H_];

// ---------------- helpers ----------------------------------------------------
__device__ __forceinline__ uint32_t smem_u32(const void* p) {
    return (uint32_t)__cvta_generic_to_shared(p);
}
static __device__ __forceinline__ void ldsm_x4(uint32_t addr, uint32_t r[4]) {
    asm volatile("ldmatrix.sync.aligned.m8n8.x4.shared.b16 {%0,%1,%2,%3},[%4];"
                 : "=r"(r[0]), "=r"(r[1]), "=r"(r[2]), "=r"(r[3]) : "r"(addr));
}
static __device__ __forceinline__ void mma16816(float d[4], const uint32_t a[4],
                                                uint32_t b0, uint32_t b1) {
    asm volatile(
        "mma.sync.aligned.m16n8k16.row.col.f32.f16.f16.f32 "
        "{%0,%1,%2,%3},{%4,%5,%6,%7},{%8,%9},{%0,%1,%2,%3};"
        : "+f"(d[0]), "+f"(d[1]), "+f"(d[2]), "+f"(d[3])
        : "r"(a[0]), "r"(a[1]), "r"(a[2]), "r"(a[3]), "r"(b0), "r"(b1));
}
static __device__ __forceinline__ uint32_t pack_h2(float a, float b) {
    __half2 h = __floats2half2_rn(a, b);
    return *(uint32_t*)&h;
}
static __device__ __forceinline__ void cp16(uint32_t dst, const void* src) {
    asm volatile("cp.async.ca.shared.global [%0],[%1],16;" ::"r"(dst), "l"(src));
}
static __device__ __forceinline__ void cp_commit() {
    asm volatile("cp.async.commit_group;" ::: "memory");
}
static __device__ __forceinline__ void cp_wait0() {
    asm volatile("cp.async.wait_group 0;" ::: "memory");
}
static __device__ __forceinline__ void mbar_init(uint32_t a, uint32_t cnt) {
    asm volatile("mbarrier.init.shared.b64 [%0], %1;" ::"r"(a), "r"(cnt) : "memory");
}
static __device__ __forceinline__ void mbar_arrive(uint32_t a) {
    asm volatile("mbarrier.arrive.shared.b64 _, [%0];" ::"r"(a) : "memory");
}
static __device__ __forceinline__ void mbar_wait(uint32_t a, uint32_t parity) {
    uint32_t done = 0;
    while (!done) {
        asm volatile(
            "{\n\t.reg .pred p;\n\t"
            "mbarrier.try_wait.parity.acquire.cta.shared::cta.b64 p, [%1], %2, 0x989680;\n\t"
            "selp.b32 %0,1,0,p;\n\t}"
            : "=r"(done) : "r"(a), "r"(parity) : "memory");
    }
}

// SMEM tile geometry: fp16, single plane. rows padded to 80B (64B data + 16B)
#define ROWB      80
#define PLANE_SZ  (128 * ROWB)          // 10240
#define A_OFF 0
#define B_OFF PLANE_SZ
#define STAGE_SZ  (2 * PLANE_SZ)        // 20480
#define NSTAGE 4
#define BAR_OFF (NSTAGE * STAGE_SZ)     // 81920
#define SMEM_TOTAL (BAR_OFF + 128)

// ---------------- routing ---------------------------------------------------
__global__ void router_kernel(const float* __restrict__ logits) {
    int tid = threadIdx.x;
    for (int t = tid; t < T_; t += 512) {
        const float* l = logits + t * E_;
        float v[E_];
#pragma unroll
        for (int e = 0; e < E_; e++) v[e] = l[e];
        int i1 = 0; float m1 = v[0];
#pragma unroll
        for (int e = 1; e < E_; e++) if (v[e] > m1) { m1 = v[e]; i1 = e; }
        int i2 = -1; float m2 = -1e30f;
#pragma unroll
        for (int e = 0; e < E_; e++) if (e != i1 && v[e] > m2) { m2 = v[e]; i2 = e; }
        float w0 = 1.f / (1.f + __expf(m2 - m1));
        g_topi[2 * t] = i1; g_topi[2 * t + 1] = i2;
        g_topw[2 * t] = w0; g_topw[2 * t + 1] = 1.f - w0;
    }
    __syncthreads();
    int wid = tid >> 5, lane = tid & 31;
    if (wid < E_) {
        int e = wid, base = 0;
        for (int j0 = 0; j0 < TK_; j0 += 32) {
            int j = j0 + lane;
            int rid = g_topi[j];
            unsigned m = __ballot_sync(0xffffffffu, rid == e);
            if (rid == e) {
                int p = base + __popc(m & ((1u << lane) - 1u));
                if (p < C_) {
                    g_slot_tok[e * C_ + p] = j >> 1;
                    g_slot_of_j[j] = e * C_ + p;
                } else g_slot_of_j[j] = -1;
            }
            base += __popc(m);
        }
        if (lane == 0) g_cnt[e] = base < C_ ? base : C_;
    }
}

// ---------------- prepass: gather x rows -> fp16 xbuf ------------------------
__global__ __launch_bounds__(256) void prepass_kernel(const float* __restrict__ x) {
    int e = blockIdx.x >> 2, row0 = (blockIdx.x & 3) << 7;
    int cnt = g_cnt[e];
    if (row0 >= cnt) return;
    int k0 = blockIdx.y * (H_ / 4);   // 512-col slab
    int wid = threadIdx.x >> 5, lane = threadIdx.x & 31;
    for (int r = row0 + wid; r < row0 + 128; r += 8) {
        bool v = r < cnt;
        const float* src = v ? x + (size_t)g_slot_tok[e * C_ + r] * H_ : nullptr;
        size_t dst = (size_t)(e * C_ + r) * H_;
        for (int k = k0 + lane * 4; k < k0 + H_ / 4; k += 128) {
            float4 f = v ? *(const float4*)(src + k) : make_float4(0, 0, 0, 0);
            *(uint2*)(g_xb + dst + k) = make_uint2(pack_h2(f.x, f.y), pack_h2(f.z, f.w));
        }
    }
}

// ---------------- consumer mma over one smem stage ---------------------------
// Warp tile 32 rows x 64 B-rows, single fp16 plane. acc[2][8][4].
static __device__ __forceinline__ void mma_stage(uint32_t sst, int mbase, int nbase,
                                                 int lane, float acc[2][8][4]) {
    int a_row = lane & 15, a_kh = lane >> 4;
    int b_mat = lane >> 3, b_r = lane & 7;
    int b_radd = (b_mat & 2) ? 8 : 0, b_kh = b_mat & 1;
#pragma unroll
    for (int k16 = 0; k16 < 2; k16++) {
        uint32_t ah[2][4];
#pragma unroll
        for (int mt = 0; mt < 2; mt++) {
            uint32_t ao = (mbase + mt * 16 + a_row) * ROWB + k16 * 32 + a_kh * 16;
            ldsm_x4(sst + A_OFF + ao, ah[mt]);
        }
#pragma unroll
        for (int pj = 0; pj < 4; pj++) {
            uint32_t bh[4];
            uint32_t bo = (nbase + pj * 16 + b_radd + b_r) * ROWB + k16 * 32 + b_kh * 16;
            ldsm_x4(sst + B_OFF + bo, bh);
#pragma unroll
            for (int t = 0; t < 2; t++) {
                int nt = 2 * pj + t;
#pragma unroll
                for (int mt = 0; mt < 2; mt++)
                    mma16816(acc[mt][nt], ah[mt], bh[2 * t], bh[2 * t + 1]);
            }
        }
    }
}

// ---------------- warp-specialized GEMM body ---------------------------------
// 256 consumer threads (8 warps, 4M x 2N of 32x64) + 128 producer threads.
template <typename F>
static __device__ __forceinline__ void gemm_ws(uint32_t sb, int NCH, int Kdim,
                                               const __half* ah, F rowptr,
                                               float acc[2][8][4]) {
    const int tid = threadIdx.x;
    if (tid == 0) {
#pragma unroll
        for (int s = 0; s < NSTAGE; s++) {
            mbar_init(sb + BAR_OFF + s * 8, 128);        // full: producers arrive
            mbar_init(sb + BAR_OFF + 64 + s * 8, 256);   // empty: consumers arrive
        }
    }
    __syncthreads();

    if (tid < 256) {
        // ---- consumer ----
        const int lane = tid & 31, wid = tid >> 5;
        const int mbase = (wid & 3) * 32, nbase = (wid >> 2) * 64;
        for (int c = 0; c < NCH; c++) {
            int s = c & (NSTAGE - 1), r = c >> 2;
            mbar_wait(sb + BAR_OFF + s * 8, r & 1);
            mma_stage(sb + s * STAGE_SZ, mbase, nbase, lane, acc);
            mbar_arrive(sb + BAR_OFF + 64 + s * 8);
        }
    } else {
        // ---- producer ----
        const int ptid = tid - 256;
        const float* rp = rowptr(ptid);
        float4 breg[8];
#pragma unroll
        for (int q = 0; q < 8; q++) breg[q] = *(const float4*)(rp + q * 4);
        for (int c = 0; c < NCH; c++) {
            int s = c & (NSTAGE - 1), r = c >> 2;
            if (r > 0) mbar_wait(sb + BAR_OFF + 64 + s * 8, (r - 1) & 1);
            uint32_t sst = sb + s * STAGE_SZ;
            // A: fp16, 128 rows x 64B -> 512 granules of 16B
#pragma unroll
            for (int j = 0; j < 4; j++) {
                int g = ptid + 128 * j;
                int row = g >> 2, seg = g & 3;
                const __half* src = ah + (size_t)row * Kdim + c * 32 + seg * 8;
                cp16(sst + A_OFF + row * ROWB + seg * 16, src);
            }
            cp_commit();
            // B: convert prefetched fp32 regs -> fp16, one row per producer thread
            uint32_t h[16];
#pragma unroll
            for (int q = 0; q < 8; q++) {
                h[2 * q]     = pack_h2(breg[q].x, breg[q].y);
                h[2 * q + 1] = pack_h2(breg[q].z, breg[q].w);
            }
            uint32_t bd = sst + B_OFF + ptid * ROWB;
#pragma unroll
            for (int m = 0; m < 4; m++) {
                asm volatile("st.shared.v4.b32 [%0],{%1,%2,%3,%4};" ::"r"(bd + 16 * m),
                             "r"(h[4 * m]), "r"(h[4 * m + 1]), "r"(h[4 * m + 2]),
                             "r"(h[4 * m + 3]));
            }
            // prefetch next chunk's B
            if (c + 1 < NCH) {
                const float* np = rp + (c + 1) * 32;
#pragma unroll
                for (int q = 0; q < 8; q++) breg[q] = *(const float4*)(np + q * 4);
            }
            cp_wait0();
            mbar_arrive(sb + BAR_OFF + s * 8);
        }
    }
}

// ---------------- GEMM1: xbuf @ w13^T (gate/up interleaved), SiLU -> act -----
__global__ __launch_bounds__(384, 1) void gemm1_mma(const float* __restrict__ w13) {
    extern __shared__ char smem[];
    const int e = blockIdx.y >> 2;
    const int row0 = (blockIdx.y & 3) << 7;
    const int cnt = g_cnt[e];
    if (row0 >= cnt) return;
    const int n0 = blockIdx.x << 6;   // 64 I-cols (128 interleaved B-rows)
    uint32_t sb = smem_u32(smem);

    const __half* ah = g_xb + (size_t)(e * C_ + row0) * H_;
    const float* wbase = w13 + (size_t)e * 2 * I_ * H_;
    auto rowptr = [&](int rb) {
        int grow = (rb & 1) ? (I_ + n0 + (rb >> 1)) : (n0 + (rb >> 1));
        return wbase + (size_t)grow * H_;
    };

    float acc[2][8][4];
#pragma unroll
    for (int a = 0; a < 2; a++)
#pragma unroll
        for (int b = 0; b < 8; b++)
#pragma unroll
            for (int c = 0; c < 4; c++) acc[a][b][c] = 0.f;

    gemm_ws(sb, H_ / 32, H_, ah, rowptr, acc);

    const int tid = threadIdx.x;
    if (tid < 256) {
        const int lane = tid & 31, wid = tid >> 5;
        const int mbase = (wid & 3) * 32, nbase = (wid >> 2) * 64;
#pragma unroll
        for (int mt = 0; mt < 2; mt++) {
#pragma unroll
            for (int half = 0; half < 2; half++) {
                int r = row0 + mbase + mt * 16 + (lane >> 2) + half * 8;
                if (r < cnt) {
                    size_t ob = (size_t)(e * C_ + r) * I_;
#pragma unroll
                    for (int nt = 0; nt < 8; nt++) {
                        int cn = nbase + nt * 8 + (lane & 3) * 2;
                        int icol = n0 + (cn >> 1);
                        float g = acc[mt][nt][2 * half];
                        float u = acc[mt][nt][2 * half + 1];
                        float a = g / (1.f + __expf(-g)) * u;
                        g_act[ob + icol] = __float2half_rn(a);
                    }
                }
            }
        }
    }
}

// ---------------- GEMM2: act @ w2^T -> ybuf (fp32) ---------------------------
__global__ __launch_bounds__(384, 1) void gemm2_mma(const float* __restrict__ w2) {
    extern __shared__ char smem[];
    const int e = blockIdx.y >> 2;
    const int row0 = (blockIdx.y & 3) << 7;
    const int cnt = g_cnt[e];
    if (row0 >= cnt) return;
    const int n0 = blockIdx.x << 7;   // 128 H-cols
    uint32_t sb = smem_u32(smem);

    const __half* ah = g_act + (size_t)(e * C_ + row0) * I_;
    const float* wbase = w2 + (size_t)e * H_ * I_;
    auto rowptr = [&](int rb) { return wbase + (size_t)(n0 + rb) * I_; };

    float acc[2][8][4];
#pragma unroll
    for (int a = 0; a < 2; a++)
#pragma unroll
        for (int b = 0; b < 8; b++)
#pragma unroll
            for (int c = 0; c < 4; c++) acc[a][b][c] = 0.f;

    gemm_ws(sb, I_ / 32, I_, ah, rowptr, acc);

    const int tid = threadIdx.x;
    if (tid < 256) {
        const int lane = tid & 31, wid = tid >> 5;
        const int mbase = (wid & 3) * 32, nbase = (wid >> 2) * 64;
#pragma unroll
        for (int mt = 0; mt < 2; mt++) {
#pragma unroll
            for (int half = 0; half < 2; half++) {
                int r = row0 + mbase + mt * 16 + (lane >> 2) + half * 8;
                if (r < cnt) {
                    float* ob = g_ybuf + (size_t)(e * C_ + r) * H_ + n0;
#pragma unroll
                    for (int nt = 0; nt < 8; nt++) {
                        int col = nbase + nt * 8 + (lane & 3) * 2;
                        *(float2*)(ob + col) =
                            make_float2(acc[mt][nt][2 * half], acc[mt][nt][2 * half + 1]);
                    }
                }
            }
        }
    }
}

// ---------------- combine ----------------------------------------------------
__global__ void combine_kernel(float* __restrict__ out) {
    int idx = blockIdx.x * blockDim.x + threadIdx.x;
    if (idx >= T_ * H_ / 4) return;
    int t = idx >> 9;
    int h = (idx & 511) << 2;
    float w0 = g_topw[2 * t], w1 = g_topw[2 * t + 1];
    int s0 = g_slot_of_j[2 * t], s1 = g_slot_of_j[2 * t + 1];
    float4 r = make_float4(0, 0, 0, 0);
    if (s0 >= 0) {
        float4 v = *(const float4*)(g_ybuf + (size_t)s0 * H_ + h);
        r.x += w0 * v.x; r.y += w0 * v.y; r.z += w0 * v.z; r.w += w0 * v.w;
    }
    if (s1 >= 0) {
        float4 v = *(const float4*)(g_ybuf + (size_t)s1 * H_ + h);
        r.x += w1 * v.x; r.y += w1 * v.y; r.z += w1 * v.z; r.w += w1 * v.w;
    }
    *(float4*)(out + (size_t)t * H_ + h) = r;
}

// ---------------- launch ----------------------------------------------------
extern "C" void kernel_launch(void* const* d_in, const int* in_sizes, int n_in,
                              void* d_out, int out_size) {
    const float* x      = (const float*)d_in[0];
    const float* logits = (const float*)d_in[1];
    const float* w13    = (const float*)d_in[2];
    const float* w2     = (const float*)d_in[3];
    float* out          = (float*)d_out;

    static int smem_set = 0;
    if (!smem_set) {
        cudaFuncSetAttribute(gemm1_mma, cudaFuncAttributeMaxDynamicSharedMemorySize, SMEM_TOTAL);
        cudaFuncSetAttribute(gemm2_mma, cudaFuncAttributeMaxDynamicSharedMemorySize, SMEM_TOTAL);
        smem_set = 1;
    }

    router_kernel<<<1, 512>>>(logits);
    prepass_kernel<<<dim3(E_ * (C_ / 128), 4), 256>>>(x);
    gemm1_mma<<<dim3(I_ / 64, E_ * (C_ / 128)), 384, SMEM_TOTAL>>>(w13);
    gemm2_mma<<<dim3(H_ / 128, E_ * (C_ / 128)), 384, SMEM_TOTAL>>>(w2);
    combine_kernel<<<(T_ * H_ / 4 + 255) / 256, 256>>>(out);
}

// round 15
// speedup vs baseline: 2.3124x; 1.1452x over previous
#include <cuda_runtime.h>
#include <cuda_fp16.h>
#include <cstdint>

#define T_  1024
#define H_  2048
#define I_  1408
#define E_  16
#define C_  512
#define TK_ 2048

// ---------------- scratch (device globals) ---------------------------------
__device__ int   g_topi[TK_];
__device__ float g_topw[TK_];
__device__ int   g_slot_tok[E_ * C_];
__device__ int   g_slot_of_j[TK_];
__device__ int   g_cnt[E_];
__device__ __align__(16) __half g_xb[(size_t)E_ * C_ * H_];
__device__ __align__(16) __half g_act[(size_t)E_ * C_ * I_];
__device__ float g_ybuf[(size_t)E_ * C_ * H_];

// ---------------- helpers ----------------------------------------------------
__device__ __forceinline__ uint32_t smem_u32(const void* p) {
    return (uint32_t)__cvta_generic_to_shared(p);
}
static __device__ __forceinline__ void ldsm_x4(uint32_t addr, uint32_t r[4]) {
    asm volatile("ldmatrix.sync.aligned.m8n8.x4.shared.b16 {%0,%1,%2,%3},[%4];"
                 : "=r"(r[0]), "=r"(r[1]), "=r"(r[2]), "=r"(r[3]) : "r"(addr));
}
static __device__ __forceinline__ void mma16816(float d[4], const uint32_t a[4],
                                                uint32_t b0, uint32_t b1) {
    asm volatile(
        "mma.sync.aligned.m16n8k16.row.col.f32.f16.f16.f32 "
        "{%0,%1,%2,%3},{%4,%5,%6,%7},{%8,%9},{%0,%1,%2,%3};"
        : "+f"(d[0]), "+f"(d[1]), "+f"(d[2]), "+f"(d[3])
        : "r"(a[0]), "r"(a[1]), "r"(a[2]), "r"(a[3]), "r"(b0), "r"(b1));
}
static __device__ __forceinline__ uint32_t pack_h2(float a, float b) {
    __half2 h = __floats2half2_rn(a, b);
    return *(uint32_t*)&h;
}
static __device__ __forceinline__ void cp16(uint32_t dst, const void* src) {
    asm volatile("cp.async.ca.shared.global [%0],[%1],16;" ::"r"(dst), "l"(src));
}
static __device__ __forceinline__ void cp_commit() {
    asm volatile("cp.async.commit_group;" ::: "memory");
}
static __device__ __forceinline__ void cp_wait0() {
    asm volatile("cp.async.wait_group 0;" ::: "memory");
}
static __device__ __forceinline__ void mbar_init(uint32_t a, uint32_t cnt) {
    asm volatile("mbarrier.init.shared.b64 [%0], %1;" ::"r"(a), "r"(cnt) : "memory");
}
static __device__ __forceinline__ void mbar_arrive(uint32_t a) {
    asm volatile("mbarrier.arrive.shared.b64 _, [%0];" ::"r"(a) : "memory");
}
static __device__ __forceinline__ void mbar_wait(uint32_t a, uint32_t parity) {
    uint32_t done = 0;
    while (!done) {
        asm volatile(
            "{\n\t.reg .pred p;\n\t"
            "mbarrier.try_wait.parity.acquire.cta.shared::cta.b64 p, [%1], %2, 0x989680;\n\t"
            "selp.b32 %0,1,0,p;\n\t}"
            : "=r"(done) : "r"(a), "r"(parity) : "memory");
    }
}

// SMEM tile geometry: fp16, K=64 per stage. rows = 128B data + 16B pad = 144B
// (144*row mod 128 walks all eight 16B banks -> conflict-free LDSM)
#define ROWB      144
#define PLANE_SZ  (128 * ROWB)          // 18432
#define A_OFF 0
#define B_OFF PLANE_SZ
#define STAGE_SZ  (2 * PLANE_SZ)        // 36864
#define NSTAGE 4
#define BAR_OFF (NSTAGE * STAGE_SZ)     // 147456
#define SMEM_TOTAL (BAR_OFF + 128)      // 147584

// ---------------- routing ---------------------------------------------------
__global__ void router_kernel(const float* __restrict__ logits) {
    int tid = threadIdx.x;
    for (int t = tid; t < T_; t += 512) {
        const float* l = logits + t * E_;
        float v[E_];
#pragma unroll
        for (int e = 0; e < E_; e++) v[e] = l[e];
        int i1 = 0; float m1 = v[0];
#pragma unroll
        for (int e = 1; e < E_; e++) if (v[e] > m1) { m1 = v[e]; i1 = e; }
        int i2 = -1; float m2 = -1e30f;
#pragma unroll
        for (int e = 0; e < E_; e++) if (e != i1 && v[e] > m2) { m2 = v[e]; i2 = e; }
        float w0 = 1.f / (1.f + __expf(m2 - m1));
        g_topi[2 * t] = i1; g_topi[2 * t + 1] = i2;
        g_topw[2 * t] = w0; g_topw[2 * t + 1] = 1.f - w0;
    }
    __syncthreads();
    int wid = tid >> 5, lane = tid & 31;
    if (wid < E_) {
        int e = wid, base = 0;
        for (int j0 = 0; j0 < TK_; j0 += 32) {
            int j = j0 + lane;
            int rid = g_topi[j];
            unsigned m = __ballot_sync(0xffffffffu, rid == e);
            if (rid == e) {
                int p = base + __popc(m & ((1u << lane) - 1u));
                if (p < C_) {
                    g_slot_tok[e * C_ + p] = j >> 1;
                    g_slot_of_j[j] = e * C_ + p;
                } else g_slot_of_j[j] = -1;
            }
            base += __popc(m);
        }
        if (lane == 0) g_cnt[e] = base < C_ ? base : C_;
    }
}

// ---------------- prepass: gather x rows -> fp16 xbuf ------------------------
__global__ __launch_bounds__(256) void prepass_kernel(const float* __restrict__ x) {
    int e = blockIdx.x >> 2, row0 = (blockIdx.x & 3) << 7;
    int cnt = g_cnt[e];
    if (row0 >= cnt) return;
    int k0 = blockIdx.y * (H_ / 4);   // 512-col slab
    int wid = threadIdx.x >> 5, lane = threadIdx.x & 31;
    for (int r = row0 + wid; r < row0 + 128; r += 8) {
        bool v = r < cnt;
        const float* src = v ? x + (size_t)g_slot_tok[e * C_ + r] * H_ : nullptr;
        size_t dst = (size_t)(e * C_ + r) * H_;
        for (int k = k0 + lane * 4; k < k0 + H_ / 4; k += 128) {
            float4 f = v ? *(const float4*)(src + k) : make_float4(0, 0, 0, 0);
            *(uint2*)(g_xb + dst + k) = make_uint2(pack_h2(f.x, f.y), pack_h2(f.z, f.w));
        }
    }
}

// ---------------- consumer mma over one K=64 smem stage ----------------------
// Warp tile 32 rows x 64 B-rows, single fp16 plane. acc[2][8][4].
static __device__ __forceinline__ void mma_stage(uint32_t sst, int mbase, int nbase,
                                                 int lane, float acc[2][8][4]) {
    int a_row = lane & 15, a_kh = lane >> 4;
    int b_mat = lane >> 3, b_r = lane & 7;
    int b_radd = (b_mat & 2) ? 8 : 0, b_kh = b_mat & 1;
#pragma unroll
    for (int k16 = 0; k16 < 4; k16++) {
        uint32_t ah[2][4];
#pragma unroll
        for (int mt = 0; mt < 2; mt++) {
            uint32_t ao = (mbase + mt * 16 + a_row) * ROWB + k16 * 32 + a_kh * 16;
            ldsm_x4(sst + A_OFF + ao, ah[mt]);
        }
#pragma unroll
        for (int pj = 0; pj < 4; pj++) {
            uint32_t bh[4];
            uint32_t bo = (nbase + pj * 16 + b_radd + b_r) * ROWB + k16 * 32 + b_kh * 16;
            ldsm_x4(sst + B_OFF + bo, bh);
#pragma unroll
            for (int t = 0; t < 2; t++) {
                int nt = 2 * pj + t;
#pragma unroll
                for (int mt = 0; mt < 2; mt++)
                    mma16816(acc[mt][nt], ah[mt], bh[2 * t], bh[2 * t + 1]);
            }
        }
    }
}

// ---------------- warp-specialized GEMM body ---------------------------------
// 256 consumer threads (8 warps, 4M x 2N of 32x64) + 128 producer threads.
// K=64 per stage: half the sync rate of the K=32 version.
template <typename F>
static __device__ __forceinline__ void gemm_ws(uint32_t sb, int NCH, int Kdim,
                                               const __half* ah, F rowptr,
                                               float acc[2][8][4]) {
    const int tid = threadIdx.x;
    if (tid == 0) {
#pragma unroll
        for (int s = 0; s < NSTAGE; s++) {
            mbar_init(sb + BAR_OFF + s * 8, 128);        // full: producers arrive
            mbar_init(sb + BAR_OFF + 64 + s * 8, 256);   // empty: consumers arrive
        }
    }
    __syncthreads();

    if (tid < 256) {
        // ---- consumer ----
        const int lane = tid & 31, wid = tid >> 5;
        const int mbase = (wid & 3) * 32, nbase = (wid >> 2) * 64;
        for (int c = 0; c < NCH; c++) {
            int s = c & (NSTAGE - 1), r = c >> 2;
            mbar_wait(sb + BAR_OFF + s * 8, r & 1);
            mma_stage(sb + s * STAGE_SZ, mbase, nbase, lane, acc);
            mbar_arrive(sb + BAR_OFF + 64 + s * 8);
        }
    } else {
        // ---- producer ----
        const int ptid = tid - 256;
        const float* rp = rowptr(ptid);
        float4 breg[16];
#pragma unroll
        for (int q = 0; q < 16; q++) breg[q] = *(const float4*)(rp + q * 4);
        for (int c = 0; c < NCH; c++) {
            int s = c & (NSTAGE - 1), r = c >> 2;
            if (r > 0) mbar_wait(sb + BAR_OFF + 64 + s * 8, (r - 1) & 1);
            uint32_t sst = sb + s * STAGE_SZ;
            // A: fp16, 128 rows x 128B -> 1024 granules of 16B, 8 per thread
#pragma unroll
            for (int j = 0; j < 8; j++) {
                int g = ptid + 128 * j;
                int row = g >> 3, seg = g & 7;
                const __half* src = ah + (size_t)row * Kdim + c * 64 + seg * 8;
                cp16(sst + A_OFF + row * ROWB + seg * 16, src);
            }
            cp_commit();
            // B: convert prefetched fp32 regs -> fp16, one 64-float row per thread
            uint32_t h[32];
#pragma unroll
            for (int q = 0; q < 16; q++) {
                h[2 * q]     = pack_h2(breg[q].x, breg[q].y);
                h[2 * q + 1] = pack_h2(breg[q].z, breg[q].w);
            }
            uint32_t bd = sst + B_OFF + ptid * ROWB;
#pragma unroll
            for (int m = 0; m < 8; m++) {
                asm volatile("st.shared.v4.b32 [%0],{%1,%2,%3,%4};" ::"r"(bd + 16 * m),
                             "r"(h[4 * m]), "r"(h[4 * m + 1]), "r"(h[4 * m + 2]),
                             "r"(h[4 * m + 3]));
            }
            // prefetch next chunk's B
            if (c + 1 < NCH) {
                const float* np = rp + (c + 1) * 64;
#pragma unroll
                for (int q = 0; q < 16; q++) breg[q] = *(const float4*)(np + q * 4);
            }
            cp_wait0();
            mbar_arrive(sb + BAR_OFF + s * 8);
        }
    }
}

// ---------------- GEMM1: xbuf @ w13^T (gate/up interleaved), SiLU -> act -----
__global__ __launch_bounds__(384, 1) void gemm1_mma(const float* __restrict__ w13) {
    extern __shared__ char smem[];
    const int e = blockIdx.y >> 2;
    const int row0 = (blockIdx.y & 3) << 7;
    const int cnt = g_cnt[e];
    if (row0 >= cnt) return;
    const int n0 = blockIdx.x << 6;   // 64 I-cols (128 interleaved B-rows)
    uint32_t sb = smem_u32(smem);

    const __half* ah = g_xb + (size_t)(e * C_ + row0) * H_;
    const float* wbase = w13 + (size_t)e * 2 * I_ * H_;
    auto rowptr = [&](int rb) {
        int grow = (rb & 1) ? (I_ + n0 + (rb >> 1)) : (n0 + (rb >> 1));
        return wbase + (size_t)grow * H_;
    };

    float acc[2][8][4];
#pragma unroll
    for (int a = 0; a < 2; a++)
#pragma unroll
        for (int b = 0; b < 8; b++)
#pragma unroll
            for (int c = 0; c < 4; c++) acc[a][b][c] = 0.f;

    gemm_ws(sb, H_ / 64, H_, ah, rowptr, acc);

    const int tid = threadIdx.x;
    if (tid < 256) {
        const int lane = tid & 31, wid = tid >> 5;
        const int mbase = (wid & 3) * 32, nbase = (wid >> 2) * 64;
#pragma unroll
        for (int mt = 0; mt < 2; mt++) {
#pragma unroll
            for (int half = 0; half < 2; half++) {
                int r = row0 + mbase + mt * 16 + (lane >> 2) + half * 8;
                if (r < cnt) {
                    size_t ob = (size_t)(e * C_ + r) * I_;
#pragma unroll
                    for (int nt = 0; nt < 8; nt++) {
                        int cn = nbase + nt * 8 + (lane & 3) * 2;
                        int icol = n0 + (cn >> 1);
                        float g = acc[mt][nt][2 * half];
                        float u = acc[mt][nt][2 * half + 1];
                        float a = g / (1.f + __expf(-g)) * u;
                        g_act[ob + icol] = __float2half_rn(a);
                    }
                }
            }
        }
    }
}

// ---------------- GEMM2: act @ w2^T -> ybuf (fp32) ---------------------------
__global__ __launch_bounds__(384, 1) void gemm2_mma(const float* __restrict__ w2) {
    extern __shared__ char smem[];
    const int e = blockIdx.y >> 2;
    const int row0 = (blockIdx.y & 3) << 7;
    const int cnt = g_cnt[e];
    if (row0 >= cnt) return;
    const int n0 = blockIdx.x << 7;   // 128 H-cols
    uint32_t sb = smem_u32(smem);

    const __half* ah = g_act + (size_t)(e * C_ + row0) * I_;
    const float* wbase = w2 + (size_t)e * H_ * I_;
    auto rowptr = [&](int rb) { return wbase + (size_t)(n0 + rb) * I_; };

    float acc[2][8][4];
#pragma unroll
    for (int a = 0; a < 2; a++)
#pragma unroll
        for (int b = 0; b < 8; b++)
#pragma unroll
            for (int c = 0; c < 4; c++) acc[a][b][c] = 0.f;

    gemm_ws(sb, I_ / 64, I_, ah, rowptr, acc);

    const int tid = threadIdx.x;
    if (tid < 256) {
        const int lane = tid & 31, wid = tid >> 5;
        const int mbase = (wid & 3) * 32, nbase = (wid >> 2) * 64;
#pragma unroll
        for (int mt = 0; mt < 2; mt++) {
#pragma unroll
            for (int half = 0; half < 2; half++) {
                int r = row0 + mbase + mt * 16 + (lane >> 2) + half * 8;
                if (r < cnt) {
                    float* ob = g_ybuf + (size_t)(e * C_ + r) * H_ + n0;
#pragma unroll
                    for (int nt = 0; nt < 8; nt++) {
                        int col = nbase + nt * 8 + (lane & 3) * 2;
                        *(float2*)(ob + col) =
                            make_float2(acc[mt][nt][2 * half], acc[mt][nt][2 * half + 1]);
                    }
                }
            }
        }
    }
}

// ---------------- combine ----------------------------------------------------
__global__ void combine_kernel(float* __restrict__ out) {
    int idx = blockIdx.x * blockDim.x + threadIdx.x;
    if (idx >= T_ * H_ / 4) return;
    int t = idx >> 9;
    int h = (idx & 511) << 2;
    float w0 = g_topw[2 * t], w1 = g_topw[2 * t + 1];
    int s0 = g_slot_of_j[2 * t], s1 = g_slot_of_j[2 * t + 1];
    float4 r = make_float4(0, 0, 0, 0);
    if (s0 >= 0) {
        float4 v = *(const float4*)(g_ybuf + (size_t)s0 * H_ + h);
        r.x += w0 * v.x; r.y += w0 * v.y; r.z += w0 * v.z; r.w += w0 * v.w;
    }
    if (s1 >= 0) {
        float4 v = *(const float4*)(g_ybuf + (size_t)s1 * H_ + h);
        r.x += w1 * v.x; r.y += w1 * v.y; r.z += w1 * v.z; r.w += w1 * v.w;
    }
    *(float4*)(out + (size_t)t * H_ + h) = r;
}

// ---------------- launch ----------------------------------------------------
extern "C" void kernel_launch(void* const* d_in, const int* in_sizes, int n_in,
                              void* d_out, int out_size) {
    const float* x      = (const float*)d_in[0];
    const float* logits = (const float*)d_in[1];
    const float* w13    = (const float*)d_in[2];
    const float* w2     = (const float*)d_in[3];
    float* out          = (float*)d_out;

    static int smem_set = 0;
    if (!smem_set) {
        cudaFuncSetAttribute(gemm1_mma, cudaFuncAttributeMaxDynamicSharedMemorySize, SMEM_TOTAL);
        cudaFuncSetAttribute(gemm2_mma, cudaFuncAttributeMaxDynamicSharedMemorySize, SMEM_TOTAL);
        smem_set = 1;
    }

    router_kernel<<<1, 512>>>(logits);
    prepass_kernel<<<dim3(E_ * (C_ / 128), 4), 256>>>(x);
    gemm1_mma<<<dim3(I_ / 64, E_ * (C_ / 128)), 384, SMEM_TOTAL>>>(w13);
    gemm2_mma<<<dim3(H_ / 128, E_ * (C_ / 128)), 384, SMEM_TOTAL>>>(w2);
    combine_kernel<<<(T_ * H_ / 4 + 255) / 256, 256>>>(out);
}

// round 16
// speedup vs baseline: 2.3145x; 1.0009x over previous
#include <cuda_runtime.h>
#include <cuda_fp16.h>
#include <cstdint>

#define T_  1024
#define H_  2048
#define I_  1408
#define E_  16
#define C_  512
#define TK_ 2048

// ---------------- scratch (device globals) ---------------------------------
__device__ int   g_topi[TK_];
__device__ float g_topw[TK_];
__device__ int   g_slot_tok[E_ * C_];
__device__ int   g_slot_of_j[TK_];
__device__ int   g_cnt[E_];
__device__ __align__(16) __half g_xb[(size_t)E_ * C_ * H_];
__device__ __align__(16) __half g_act[(size_t)E_ * C_ * I_];
__device__ float g_ybuf[(size_t)E_ * C_ * H_];

// ---------------- helpers ----------------------------------------------------
__device__ __forceinline__ uint32_t smem_u32(const void* p) {
    return (uint32_t)__cvta_generic_to_shared(p);
}
static __device__ __forceinline__ void ldsm_x4(uint32_t addr, uint32_t r[4]) {
    asm volatile("ldmatrix.sync.aligned.m8n8.x4.shared.b16 {%0,%1,%2,%3},[%4];"
                 : "=r"(r[0]), "=r"(r[1]), "=r"(r[2]), "=r"(r[3]) : "r"(addr));
}
static __device__ __forceinline__ void mma16816(float d[4], const uint32_t a[4],
                                                uint32_t b0, uint32_t b1) {
    asm volatile(
        "mma.sync.aligned.m16n8k16.row.col.f32.f16.f16.f32 "
        "{%0,%1,%2,%3},{%4,%5,%6,%7},{%8,%9},{%0,%1,%2,%3};"
        : "+f"(d[0]), "+f"(d[1]), "+f"(d[2]), "+f"(d[3])
        : "r"(a[0]), "r"(a[1]), "r"(a[2]), "r"(a[3]), "r"(b0), "r"(b1));
}
static __device__ __forceinline__ uint32_t pack_h2(float a, float b) {
    __half2 h = __floats2half2_rn(a, b);
    return *(uint32_t*)&h;
}
static __device__ __forceinline__ void cp16(uint32_t dst, const void* src) {
    asm volatile("cp.async.ca.shared.global [%0],[%1],16;" ::"r"(dst), "l"(src));
}
static __device__ __forceinline__ void cp_commit() {
    asm volatile("cp.async.commit_group;" ::: "memory");
}
static __device__ __forceinline__ void cp_wait0() {
    asm volatile("cp.async.wait_group 0;" ::: "memory");
}
static __device__ __forceinline__ void mbar_init(uint32_t a, uint32_t cnt) {
    asm volatile("mbarrier.init.shared.b64 [%0], %1;" ::"r"(a), "r"(cnt) : "memory");
}
static __device__ __forceinline__ void mbar_arrive(uint32_t a) {
    asm volatile("mbarrier.arrive.shared.b64 _, [%0];" ::"r"(a) : "memory");
}
static __device__ __forceinline__ void mbar_wait(uint32_t a, uint32_t parity) {
    uint32_t done = 0;
    while (!done) {
        asm volatile(
            "{\n\t.reg .pred p;\n\t"
            "mbarrier.try_wait.parity.acquire.cta.shared::cta.b64 p, [%1], %2, 0x989680;\n\t"
            "selp.b32 %0,1,0,p;\n\t}"
            : "=r"(done) : "r"(a), "r"(parity) : "memory");
    }
}

// SMEM tile geometry: fp16, K=64 per stage. rows = 128B data + 16B pad = 144B
#define ROWB      144
#define PLANE_SZ  (128 * ROWB)          // 18432
#define A_OFF 0
#define B_OFF PLANE_SZ
#define STAGE_SZ  (2 * PLANE_SZ)        // 36864
#define NSTAGE 4
#define BAR_OFF (NSTAGE * STAGE_SZ)     // 147456
#define SMEM_TOTAL (BAR_OFF + 128)      // 147584

// ---------------- routing ---------------------------------------------------
__global__ void router_kernel(const float* __restrict__ logits) {
    int tid = threadIdx.x;
    for (int t = tid; t < T_; t += 512) {
        const float* l = logits + t * E_;
        float v[E_];
#pragma unroll
        for (int e = 0; e < E_; e++) v[e] = l[e];
        int i1 = 0; float m1 = v[0];
#pragma unroll
        for (int e = 1; e < E_; e++) if (v[e] > m1) { m1 = v[e]; i1 = e; }
        int i2 = -1; float m2 = -1e30f;
#pragma unroll
        for (int e = 0; e < E_; e++) if (e != i1 && v[e] > m2) { m2 = v[e]; i2 = e; }
        float w0 = 1.f / (1.f + __expf(m2 - m1));
        g_topi[2 * t] = i1; g_topi[2 * t + 1] = i2;
        g_topw[2 * t] = w0; g_topw[2 * t + 1] = 1.f - w0;
    }
    __syncthreads();
    int wid = tid >> 5, lane = tid & 31;
    if (wid < E_) {
        int e = wid, base = 0;
        for (int j0 = 0; j0 < TK_; j0 += 32) {
            int j = j0 + lane;
            int rid = g_topi[j];
            unsigned m = __ballot_sync(0xffffffffu, rid == e);
            if (rid == e) {
                int p = base + __popc(m & ((1u << lane) - 1u));
                if (p < C_) {
                    g_slot_tok[e * C_ + p] = j >> 1;
                    g_slot_of_j[j] = e * C_ + p;
                } else g_slot_of_j[j] = -1;
            }
            base += __popc(m);
        }
        if (lane == 0) g_cnt[e] = base < C_ ? base : C_;
    }
}

// ---------------- prepass: gather x rows -> fp16 xbuf ------------------------
__global__ __launch_bounds__(256) void prepass_kernel(const float* __restrict__ x) {
    int e = blockIdx.x >> 2, row0 = (blockIdx.x & 3) << 7;
    int cnt = g_cnt[e];
    if (row0 >= cnt) return;
    int k0 = blockIdx.y * (H_ / 4);   // 512-col slab
    int wid = threadIdx.x >> 5, lane = threadIdx.x & 31;
    for (int r = row0 + wid; r < row0 + 128; r += 8) {
        bool v = r < cnt;
        const float* src = v ? x + (size_t)g_slot_tok[e * C_ + r] * H_ : nullptr;
        size_t dst = (size_t)(e * C_ + r) * H_;
        for (int k = k0 + lane * 4; k < k0 + H_ / 4; k += 128) {
            float4 f = v ? *(const float4*)(src + k) : make_float4(0, 0, 0, 0);
            *(uint2*)(g_xb + dst + k) = make_uint2(pack_h2(f.x, f.y), pack_h2(f.z, f.w));
        }
    }
}

// ---------------- consumer mma over one K=64 smem stage ----------------------
// Warp tile 32 rows x 64 B-rows, single fp16 plane. acc[2][8][4].
static __device__ __forceinline__ void mma_stage(uint32_t sst, int mbase, int nbase,
                                                 int lane, float acc[2][8][4]) {
    int a_row = lane & 15, a_kh = lane >> 4;
    int b_mat = lane >> 3, b_r = lane & 7;
    int b_radd = (b_mat & 2) ? 8 : 0, b_kh = b_mat & 1;
#pragma unroll
    for (int k16 = 0; k16 < 4; k16++) {
        uint32_t ah[2][4];
#pragma unroll
        for (int mt = 0; mt < 2; mt++) {
            uint32_t ao = (mbase + mt * 16 + a_row) * ROWB + k16 * 32 + a_kh * 16;
            ldsm_x4(sst + A_OFF + ao, ah[mt]);
        }
#pragma unroll
        for (int pj = 0; pj < 4; pj++) {
            uint32_t bh[4];
            uint32_t bo = (nbase + pj * 16 + b_radd + b_r) * ROWB + k16 * 32 + b_kh * 16;
            ldsm_x4(sst + B_OFF + bo, bh);
#pragma unroll
            for (int t = 0; t < 2; t++) {
                int nt = 2 * pj + t;
#pragma unroll
                for (int mt = 0; mt < 2; mt++)
                    mma16816(acc[mt][nt], ah[mt], bh[2 * t], bh[2 * t + 1]);
            }
        }
    }
}

// ---------------- warp-specialized GEMM body ---------------------------------
// 256 consumer threads (8 warps, 4M x 2N of 32x64) + 128 producer threads.
// Warp-elected mbarrier arrives: full count=4 (producer warps), empty count=8
// (consumer warps) -- removes the per-chunk 384-thread arrive storm on a
// single SMEM atomic word.
template <typename F>
static __device__ __forceinline__ void gemm_ws(uint32_t sb, int NCH, int Kdim,
                                               const __half* ah, F rowptr,
                                               float acc[2][8][4]) {
    const int tid = threadIdx.x;
    if (tid == 0) {
#pragma unroll
        for (int s = 0; s < NSTAGE; s++) {
            mbar_init(sb + BAR_OFF + s * 8, 4);          // full: 4 producer warps
            mbar_init(sb + BAR_OFF + 64 + s * 8, 8);     // empty: 8 consumer warps
        }
    }
    __syncthreads();
    const int lane = tid & 31;

    if (tid < 256) {
        // ---- consumer ----
        const int wid = tid >> 5;
        const int mbase = (wid & 3) * 32, nbase = (wid >> 2) * 64;
        for (int c = 0; c < NCH; c++) {
            int s = c & (NSTAGE - 1), r = c >> 2;
            mbar_wait(sb + BAR_OFF + s * 8, r & 1);
            mma_stage(sb + s * STAGE_SZ, mbase, nbase, lane, acc);
            if (lane == 0) mbar_arrive(sb + BAR_OFF + 64 + s * 8);
        }
    } else {
        // ---- producer ----
        const int ptid = tid - 256;
        const float* rp = rowptr(ptid);
        float4 breg[16];
#pragma unroll
        for (int q = 0; q < 16; q++) breg[q] = *(const float4*)(rp + q * 4);
        for (int c = 0; c < NCH; c++) {
            int s = c & (NSTAGE - 1), r = c >> 2;
            if (r > 0) mbar_wait(sb + BAR_OFF + 64 + s * 8, (r - 1) & 1);
            uint32_t sst = sb + s * STAGE_SZ;
            // A: fp16, 128 rows x 128B -> 1024 granules of 16B, 8 per thread
#pragma unroll
            for (int j = 0; j < 8; j++) {
                int g = ptid + 128 * j;
                int row = g >> 3, seg = g & 7;
                const __half* src = ah + (size_t)row * Kdim + c * 64 + seg * 8;
                cp16(sst + A_OFF + row * ROWB + seg * 16, src);
            }
            cp_commit();
            // B: convert prefetched fp32 regs -> fp16, one 64-float row per thread
            uint32_t h[32];
#pragma unroll
            for (int q = 0; q < 16; q++) {
                h[2 * q]     = pack_h2(breg[q].x, breg[q].y);
                h[2 * q + 1] = pack_h2(breg[q].z, breg[q].w);
            }
            uint32_t bd = sst + B_OFF + ptid * ROWB;
#pragma unroll
            for (int m = 0; m < 8; m++) {
                asm volatile("st.shared.v4.b32 [%0],{%1,%2,%3,%4};" ::"r"(bd + 16 * m),
                             "r"(h[4 * m]), "r"(h[4 * m + 1]), "r"(h[4 * m + 2]),
                             "r"(h[4 * m + 3]));
            }
            // prefetch next chunk's B
            if (c + 1 < NCH) {
                const float* np = rp + (c + 1) * 64;
#pragma unroll
                for (int q = 0; q < 16; q++) breg[q] = *(const float4*)(np + q * 4);
            }
            cp_wait0();
            __syncwarp();
            if (lane == 0) mbar_arrive(sb + BAR_OFF + s * 8);
        }
    }
}

// ---------------- GEMM1: xbuf @ w13^T (gate/up interleaved), SiLU -> act -----
__global__ __launch_bounds__(384, 1) void gemm1_mma(const float* __restrict__ w13) {
    extern __shared__ char smem[];
    const int e = blockIdx.y >> 2;
    const int row0 = (blockIdx.y & 3) << 7;
    const int cnt = g_cnt[e];
    if (row0 >= cnt) return;
    const int n0 = blockIdx.x << 6;   // 64 I-cols (128 interleaved B-rows)
    uint32_t sb = smem_u32(smem);

    const __half* ah = g_xb + (size_t)(e * C_ + row0) * H_;
    const float* wbase = w13 + (size_t)e * 2 * I_ * H_;
    auto rowptr = [&](int rb) {
        int grow = (rb & 1) ? (I_ + n0 + (rb >> 1)) : (n0 + (rb >> 1));
        return wbase + (size_t)grow * H_;
    };

    float acc[2][8][4];
#pragma unroll
    for (int a = 0; a < 2; a++)
#pragma unroll
        for (int b = 0; b < 8; b++)
#pragma unroll
            for (int c = 0; c < 4; c++) acc[a][b][c] = 0.f;

    gemm_ws(sb, H_ / 64, H_, ah, rowptr, acc);

    const int tid = threadIdx.x;
    if (tid < 256) {
        const int lane = tid & 31, wid = tid >> 5;
        const int mbase = (wid & 3) * 32, nbase = (wid >> 2) * 64;
#pragma unroll
        for (int mt = 0; mt < 2; mt++) {
#pragma unroll
            for (int half = 0; half < 2; half++) {
                int r = row0 + mbase + mt * 16 + (lane >> 2) + half * 8;
                if (r < cnt) {
                    size_t ob = (size_t)(e * C_ + r) * I_;
#pragma unroll
                    for (int nt = 0; nt < 8; nt++) {
                        int cn = nbase + nt * 8 + (lane & 3) * 2;
                        int icol = n0 + (cn >> 1);
                        float g = acc[mt][nt][2 * half];
                        float u = acc[mt][nt][2 * half + 1];
                        float a = g / (1.f + __expf(-g)) * u;
                        g_act[ob + icol] = __float2half_rn(a);
                    }
                }
            }
        }
    }
}

// ---------------- GEMM2: act @ w2^T -> ybuf (fp32) ---------------------------
__global__ __launch_bounds__(384, 1) void gemm2_mma(const float* __restrict__ w2) {
    extern __shared__ char smem[];
    const int e = blockIdx.y >> 2;
    const int row0 = (blockIdx.y & 3) << 7;
    const int cnt = g_cnt[e];
    if (row0 >= cnt) return;
    const int n0 = blockIdx.x << 7;   // 128 H-cols
    uint32_t sb = smem_u32(smem);

    const __half* ah = g_act + (size_t)(e * C_ + row0) * I_;
    const float* wbase = w2 + (size_t)e * H_ * I_;
    auto rowptr = [&](int rb) { return wbase + (size_t)(n0 + rb) * I_; };

    float acc[2][8][4];
#pragma unroll
    for (int a = 0; a < 2; a++)
#pragma unroll
        for (int b = 0; b < 8; b++)
#pragma unroll
            for (int c = 0; c < 4; c++) acc[a][b][c] = 0.f;

    gemm_ws(sb, I_ / 64, I_, ah, rowptr, acc);

    const int tid = threadIdx.x;
    if (tid < 256) {
        const int lane = tid & 31, wid = tid >> 5;
        const int mbase = (wid & 3) * 32, nbase = (wid >> 2) * 64;
#pragma unroll
        for (int mt = 0; mt < 2; mt++) {
#pragma unroll
            for (int half = 0; half < 2; half++) {
                int r = row0 + mbase + mt * 16 + (lane >> 2) + half * 8;
                if (r < cnt) {
                    float* ob = g_ybuf + (size_t)(e * C_ + r) * H_ + n0;
#pragma unroll
                    for (int nt = 0; nt < 8; nt++) {
                        int col = nbase + nt * 8 + (lane & 3) * 2;
                        *(float2*)(ob + col) =
                            make_float2(acc[mt][nt][2 * half], acc[mt][nt][2 * half + 1]);
                    }
                }
            }
        }
    }
}

// ---------------- combine ----------------------------------------------------
__global__ void combine_kernel(float* __restrict__ out) {
    int idx = blockIdx.x * blockDim.x + threadIdx.x;
    if (idx >= T_ * H_ / 4) return;
    int t = idx >> 9;
    int h = (idx & 511) << 2;
    float w0 = g_topw[2 * t], w1 = g_topw[2 * t + 1];
    int s0 = g_slot_of_j[2 * t], s1 = g_slot_of_j[2 * t + 1];
    float4 r = make_float4(0, 0, 0, 0);
    if (s0 >= 0) {
        float4 v = *(const float4*)(g_ybuf + (size_t)s0 * H_ + h);
        r.x += w0 * v.x; r.y += w0 * v.y; r.z += w0 * v.z; r.w += w0 * v.w;
    }
    if (s1 >= 0) {
        float4 v = *(const float4*)(g_ybuf + (size_t)s1 * H_ + h);
        r.x += w1 * v.x; r.y += w1 * v.y; r.z += w1 * v.z; r.w += w1 * v.w;
    }
    *(float4*)(out + (size_t)t * H_ + h) = r;
}

// ---------------- launch ----------------------------------------------------
extern "C" void kernel_launch(void* const* d_in, const int* in_sizes, int n_in,
                              void* d_out, int out_size) {
    const float* x      = (const float*)d_in[0];
    const float* logits = (const float*)d_in[1];
    const float* w13    = (const float*)d_in[2];
    const float* w2     = (const float*)d_in[3];
    float* out          = (float*)d_out;

    static int smem_set = 0;
    if (!smem_set) {
        cudaFuncSetAttribute(gemm1_mma, cudaFuncAttributeMaxDynamicSharedMemorySize, SMEM_TOTAL);
        cudaFuncSetAttribute(gemm2_mma, cudaFuncAttributeMaxDynamicSharedMemorySize, SMEM_TOTAL);
        smem_set = 1;
    }

    router_kernel<<<1, 512>>>(logits);
    prepass_kernel<<<dim3(E_ * (C_ / 128), 4), 256>>>(x);
    gemm1_mma<<<dim3(I_ / 64, E_ * (C_ / 128)), 384, SMEM_TOTAL>>>(w13);
    gemm2_mma<<<dim3(H_ / 128, E_ * (C_ / 128)), 384, SMEM_TOTAL>>>(w2);
    combine_kernel<<<(T_ * H_ / 4 + 255) / 256, 256>>>(out);
}

// round 17
// speedup vs baseline: 3.3618x; 1.4525x over previous
#include <cuda_runtime.h>
#include <cuda_fp16.h>
#include <cstdint>

#define T_  1024
#define H_  2048
#define I_  1408
#define E_  16
#define C_  512
#define TK_ 2048

// ---------------- scratch (device globals) ---------------------------------
__device__ int   g_topi[TK_];
__device__ float g_topw[TK_];
__device__ int   g_slot_tok[E_ * C_];
__device__ int   g_slot_of_j[TK_];
__device__ int   g_cnt[E_];
__device__ __align__(16) __half g_xb[(size_t)E_ * C_ * H_];
__device__ __align__(16) __half g_act[(size_t)E_ * C_ * I_];
__device__ float g_ybuf[(size_t)E_ * C_ * H_];

// ---------------- helpers ----------------------------------------------------
__device__ __forceinline__ uint32_t smem_u32(const void* p) {
    return (uint32_t)__cvta_generic_to_shared(p);
}
static __device__ __forceinline__ void ldsm_x4(uint32_t addr, uint32_t r[4]) {
    asm volatile("ldmatrix.sync.aligned.m8n8.x4.shared.b16 {%0,%1,%2,%3},[%4];"
                 : "=r"(r[0]), "=r"(r[1]), "=r"(r[2]), "=r"(r[3]) : "r"(addr));
}
static __device__ __forceinline__ void mma16816(float d[4], const uint32_t a[4],
                                                uint32_t b0, uint32_t b1) {
    asm volatile(
        "mma.sync.aligned.m16n8k16.row.col.f32.f16.f16.f32 "
        "{%0,%1,%2,%3},{%4,%5,%6,%7},{%8,%9},{%0,%1,%2,%3};"
        : "+f"(d[0]), "+f"(d[1]), "+f"(d[2]), "+f"(d[3])
        : "r"(a[0]), "r"(a[1]), "r"(a[2]), "r"(a[3]), "r"(b0), "r"(b1));
}
static __device__ __forceinline__ uint32_t pack_h2(float a, float b) {
    __half2 h = __floats2half2_rn(a, b);
    return *(uint32_t*)&h;
}
static __device__ __forceinline__ void cp16(uint32_t dst, const void* src) {
    asm volatile("cp.async.ca.shared.global [%0],[%1],16;" ::"r"(dst), "l"(src));
}
static __device__ __forceinline__ void cp_commit() {
    asm volatile("cp.async.commit_group;" ::: "memory");
}
static __device__ __forceinline__ void cp_wait0() {
    asm volatile("cp.async.wait_group 0;" ::: "memory");
}
static __device__ __forceinline__ void mbar_init(uint32_t a, uint32_t cnt) {
    asm volatile("mbarrier.init.shared.b64 [%0], %1;" ::"r"(a), "r"(cnt) : "memory");
}
static __device__ __forceinline__ void mbar_arrive(uint32_t a) {
    asm volatile("mbarrier.arrive.shared.b64 _, [%0];" ::"r"(a) : "memory");
}
static __device__ __forceinline__ void mbar_wait(uint32_t a, uint32_t parity) {
    uint32_t done = 0;
    while (!done) {
        asm volatile(
            "{\n\t.reg .pred p;\n\t"
            "mbarrier.try_wait.parity.acquire.cta.shared::cta.b64 p, [%1], %2, 0x989680;\n\t"
            "selp.b32 %0,1,0,p;\n\t}"
            : "=r"(done) : "r"(a), "r"(parity) : "memory");
    }
}

// SMEM tile geometry: fp16, K=64 per stage. rows = 128B data + 16B pad = 144B
#define ROWB      144
#define PLANE_SZ  (128 * ROWB)          // 18432
#define A_OFF 0
#define B_OFF PLANE_SZ
#define STAGE_SZ  (2 * PLANE_SZ)        // 36864
#define NSTAGE 4
#define BAR_OFF (NSTAGE * STAGE_SZ)     // 147456
#define SMEM_TOTAL (BAR_OFF + 128)      // 147584

// ---------------- routing ---------------------------------------------------
__global__ void router_kernel(const float* __restrict__ logits) {
    int tid = threadIdx.x;
    for (int t = tid; t < T_; t += 512) {
        const float* l = logits + t * E_;
        float v[E_];
#pragma unroll
        for (int e = 0; e < E_; e++) v[e] = l[e];
        int i1 = 0; float m1 = v[0];
#pragma unroll
        for (int e = 1; e < E_; e++) if (v[e] > m1) { m1 = v[e]; i1 = e; }
        int i2 = -1; float m2 = -1e30f;
#pragma unroll
        for (int e = 0; e < E_; e++) if (e != i1 && v[e] > m2) { m2 = v[e]; i2 = e; }
        float w0 = 1.f / (1.f + __expf(m2 - m1));
        g_topi[2 * t] = i1; g_topi[2 * t + 1] = i2;
        g_topw[2 * t] = w0; g_topw[2 * t + 1] = 1.f - w0;
    }
    __syncthreads();
    int wid = tid >> 5, lane = tid & 31;
    if (wid < E_) {
        int e = wid, base = 0;
        for (int j0 = 0; j0 < TK_; j0 += 32) {
            int j = j0 + lane;
            int rid = g_topi[j];
            unsigned m = __ballot_sync(0xffffffffu, rid == e);
            if (rid == e) {
                int p = base + __popc(m & ((1u << lane) - 1u));
                if (p < C_) {
                    g_slot_tok[e * C_ + p] = j >> 1;
                    g_slot_of_j[j] = e * C_ + p;
                } else g_slot_of_j[j] = -1;
            }
            base += __popc(m);
        }
        if (lane == 0) g_cnt[e] = base < C_ ? base : C_;
    }
}

// ---------------- prepass: gather x rows -> fp16 xbuf ------------------------
__global__ __launch_bounds__(256) void prepass_kernel(const float* __restrict__ x) {
    int e = blockIdx.x >> 2, row0 = (blockIdx.x & 3) << 7;
    int cnt = g_cnt[e];
    if (row0 >= cnt) return;
    int k0 = blockIdx.y * (H_ / 4);   // 512-col slab
    int wid = threadIdx.x >> 5, lane = threadIdx.x & 31;
    for (int r = row0 + wid; r < row0 + 128; r += 8) {
        bool v = r < cnt;
        const float* src = v ? x + (size_t)g_slot_tok[e * C_ + r] * H_ : nullptr;
        size_t dst = (size_t)(e * C_ + r) * H_;
        for (int k = k0 + lane * 4; k < k0 + H_ / 4; k += 128) {
            float4 f = v ? *(const float4*)(src + k) : make_float4(0, 0, 0, 0);
            *(uint2*)(g_xb + dst + k) = make_uint2(pack_h2(f.x, f.y), pack_h2(f.z, f.w));
        }
    }
}

// ---------------- consumer mma over one K=64 smem stage ----------------------
// Warp tile 32 rows x 64 B-rows, single fp16 plane. acc[2][8][4].
static __device__ __forceinline__ void mma_stage(uint32_t sst, int mbase, int nbase,
                                                 int lane, float acc[2][8][4]) {
    int a_row = lane & 15, a_kh = lane >> 4;
    int b_mat = lane >> 3, b_r = lane & 7;
    int b_radd = (b_mat & 2) ? 8 : 0, b_kh = b_mat & 1;
#pragma unroll
    for (int k16 = 0; k16 < 4; k16++) {
        uint32_t ah[2][4];
#pragma unroll
        for (int mt = 0; mt < 2; mt++) {
            uint32_t ao = (mbase + mt * 16 + a_row) * ROWB + k16 * 32 + a_kh * 16;
            ldsm_x4(sst + A_OFF + ao, ah[mt]);
        }
#pragma unroll
        for (int pj = 0; pj < 4; pj++) {
            uint32_t bh[4];
            uint32_t bo = (nbase + pj * 16 + b_radd + b_r) * ROWB + k16 * 32 + b_kh * 16;
            ldsm_x4(sst + B_OFF + bo, bh);
#pragma unroll
            for (int t = 0; t < 2; t++) {
                int nt = 2 * pj + t;
#pragma unroll
                for (int mt = 0; mt < 2; mt++)
                    mma16816(acc[mt][nt], ah[mt], bh[2 * t], bh[2 * t + 1]);
            }
        }
    }
}

// ---------------- warp-specialized GEMM body ---------------------------------
// 256 consumer threads (8 warps, 4M x 2N of 32x64) + 128 producer threads.
// COALESCED producer B loads: thread ptid loads segment (ptid&15) of rows
// (8j + (ptid>>4)), j=0..15. Each LDG.128 warp instruction touches 4 lines
// (nL=4) instead of 32 -> 8x fewer L1tex wavefronts.
// bbase: thread-specific base pointer (seg+first-row applied); jstride: float
// stride between consecutive j rows.
static __device__ __forceinline__ void gemm_ws(uint32_t sb, int NCH, int Kdim,
                                               const __half* ah, const float* bbase,
                                               int jstride, float acc[2][8][4]) {
    const int tid = threadIdx.x;
    if (tid == 0) {
#pragma unroll
        for (int s = 0; s < NSTAGE; s++) {
            mbar_init(sb + BAR_OFF + s * 8, 4);          // full: 4 producer warps
            mbar_init(sb + BAR_OFF + 64 + s * 8, 8);     // empty: 8 consumer warps
        }
    }
    __syncthreads();
    const int lane = tid & 31;

    if (tid < 256) {
        // ---- consumer ----
        const int wid = tid >> 5;
        const int mbase = (wid & 3) * 32, nbase = (wid >> 2) * 64;
        for (int c = 0; c < NCH; c++) {
            int s = c & (NSTAGE - 1), r = c >> 2;
            mbar_wait(sb + BAR_OFF + s * 8, r & 1);
            mma_stage(sb + s * STAGE_SZ, mbase, nbase, lane, acc);
            if (lane == 0) mbar_arrive(sb + BAR_OFF + 64 + s * 8);
        }
    } else {
        // ---- producer ----
        const int ptid = tid - 256;
        const int t16 = ptid >> 4, seg = ptid & 15;
        // SMEM dst for this thread's B segments: row (8j + t16), byte seg*8 (fp16)
        const uint32_t bsm = B_OFF + t16 * ROWB + seg * 8;
        float4 breg[16];
#pragma unroll
        for (int q = 0; q < 16; q++) breg[q] = *(const float4*)(bbase + q * jstride);
        for (int c = 0; c < NCH; c++) {
            int s = c & (NSTAGE - 1), r = c >> 2;
            if (r > 0) mbar_wait(sb + BAR_OFF + 64 + s * 8, (r - 1) & 1);
            uint32_t sst = sb + s * STAGE_SZ;
            // A: fp16, 128 rows x 128B -> 1024 granules of 16B, 8 per thread
#pragma unroll
            for (int j = 0; j < 8; j++) {
                int g = ptid + 128 * j;
                int row = g >> 3, sg = g & 7;
                const __half* src = ah + (size_t)row * Kdim + c * 64 + sg * 8;
                cp16(sst + A_OFF + row * ROWB + sg * 16, src);
            }
            cp_commit();
            // B: convert prefetched fp32 regs -> fp16, one 16B segment of 16 rows
#pragma unroll
            for (int q = 0; q < 16; q++) {
                uint32_t h0 = pack_h2(breg[q].x, breg[q].y);
                uint32_t h1 = pack_h2(breg[q].z, breg[q].w);
                asm volatile("st.shared.v2.b32 [%0],{%1,%2};"
                             ::"r"(sst + bsm + q * (8 * ROWB)), "r"(h0), "r"(h1));
            }
            // prefetch next chunk's B (coalesced: 16 lanes = 256B contiguous)
            if (c + 1 < NCH) {
                const float* np = bbase + (c + 1) * 64;
#pragma unroll
                for (int q = 0; q < 16; q++) breg[q] = *(const float4*)(np + q * jstride);
            }
            cp_wait0();
            __syncwarp();
            if (lane == 0) mbar_arrive(sb + BAR_OFF + s * 8);
        }
    }
}

// ---------------- GEMM1: xbuf @ w13^T (gate/up interleaved), SiLU -> act -----
__global__ __launch_bounds__(384, 1) void gemm1_mma(const float* __restrict__ w13) {
    extern __shared__ char smem[];
    const int e = blockIdx.y >> 2;
    const int row0 = (blockIdx.y & 3) << 7;
    const int cnt = g_cnt[e];
    if (row0 >= cnt) return;
    const int n0 = blockIdx.x << 6;   // 64 I-cols (128 interleaved B-rows)
    uint32_t sb = smem_u32(smem);

    const __half* ah = g_xb + (size_t)(e * C_ + row0) * H_;
    const float* wbase = w13 + (size_t)e * 2 * I_ * H_;
    // B-row rb = 8j + t16; interleave: rb&1 = t16&1, rb>>1 = 4j + (t16>>1)
    // grow = (t16&1 ? I_ + n0 : n0) + 4j + (t16>>1)  -> base + j*4*H_
    const int ptid0 = (threadIdx.x >= 256) ? (threadIdx.x - 256) : 0;
    const int t16 = ptid0 >> 4, seg = ptid0 & 15;
    const int grow0 = ((t16 & 1) ? (I_ + n0) : n0) + (t16 >> 1);
    const float* bbase = wbase + (size_t)grow0 * H_ + seg * 4;
    const int jstride = 4 * H_;

    float acc[2][8][4];
#pragma unroll
    for (int a = 0; a < 2; a++)
#pragma unroll
        for (int b = 0; b < 8; b++)
#pragma unroll
            for (int c = 0; c < 4; c++) acc[a][b][c] = 0.f;

    gemm_ws(sb, H_ / 64, H_, ah, bbase, jstride, acc);

    const int tid = threadIdx.x;
    if (tid < 256) {
        const int lane = tid & 31, wid = tid >> 5;
        const int mbase = (wid & 3) * 32, nbase = (wid >> 2) * 64;
#pragma unroll
        for (int mt = 0; mt < 2; mt++) {
#pragma unroll
            for (int half = 0; half < 2; half++) {
                int r = row0 + mbase + mt * 16 + (lane >> 2) + half * 8;
                if (r < cnt) {
                    size_t ob = (size_t)(e * C_ + r) * I_;
#pragma unroll
                    for (int nt = 0; nt < 8; nt++) {
                        int cn = nbase + nt * 8 + (lane & 3) * 2;
                        int icol = n0 + (cn >> 1);
                        float g = acc[mt][nt][2 * half];
                        float u = acc[mt][nt][2 * half + 1];
                        float a = g / (1.f + __expf(-g)) * u;
                        g_act[ob + icol] = __float2half_rn(a);
                    }
                }
            }
        }
    }
}

// ---------------- GEMM2: act @ w2^T -> ybuf (fp32) ---------------------------
__global__ __launch_bounds__(384, 1) void gemm2_mma(const float* __restrict__ w2) {
    extern __shared__ char smem[];
    const int e = blockIdx.y >> 2;
    const int row0 = (blockIdx.y & 3) << 7;
    const int cnt = g_cnt[e];
    if (row0 >= cnt) return;
    const int n0 = blockIdx.x << 7;   // 128 H-cols
    uint32_t sb = smem_u32(smem);

    const __half* ah = g_act + (size_t)(e * C_ + row0) * I_;
    const float* wbase = w2 + (size_t)e * H_ * I_;
    const int ptid0 = (threadIdx.x >= 256) ? (threadIdx.x - 256) : 0;
    const int t16 = ptid0 >> 4, seg = ptid0 & 15;
    const float* bbase = wbase + (size_t)(n0 + t16) * I_ + seg * 4;
    const int jstride = 8 * I_;

    float acc[2][8][4];
#pragma unroll
    for (int a = 0; a < 2; a++)
#pragma unroll
        for (int b = 0; b < 8; b++)
#pragma unroll
            for (int c = 0; c < 4; c++) acc[a][b][c] = 0.f;

    gemm_ws(sb, I_ / 64, I_, ah, bbase, jstride, acc);

    const int tid = threadIdx.x;
    if (tid < 256) {
        const int lane = tid & 31, wid = tid >> 5;
        const int mbase = (wid & 3) * 32, nbase = (wid >> 2) * 64;
#pragma unroll
        for (int mt = 0; mt < 2; mt++) {
#pragma unroll
            for (int half = 0; half < 2; half++) {
                int r = row0 + mbase + mt * 16 + (lane >> 2) + half * 8;
                if (r < cnt) {
                    float* ob = g_ybuf + (size_t)(e * C_ + r) * H_ + n0;
#pragma unroll
                    for (int nt = 0; nt < 8; nt++) {
                        int col = nbase + nt * 8 + (lane & 3) * 2;
                        *(float2*)(ob + col) =
                            make_float2(acc[mt][nt][2 * half], acc[mt][nt][2 * half + 1]);
                    }
                }
            }
        }
    }
}

// ---------------- combine ----------------------------------------------------
__global__ void combine_kernel(float* __restrict__ out) {
    int idx = blockIdx.x * blockDim.x + threadIdx.x;
    if (idx >= T_ * H_ / 4) return;
    int t = idx >> 9;
    int h = (idx & 511) << 2;
    float w0 = g_topw[2 * t], w1 = g_topw[2 * t + 1];
    int s0 = g_slot_of_j[2 * t], s1 = g_slot_of_j[2 * t + 1];
    float4 r = make_float4(0, 0, 0, 0);
    if (s0 >= 0) {
        float4 v = *(const float4*)(g_ybuf + (size_t)s0 * H_ + h);
        r.x += w0 * v.x; r.y += w0 * v.y; r.z += w0 * v.z; r.w += w0 * v.w;
    }
    if (s1 >= 0) {
        float4 v = *(const float4*)(g_ybuf + (size_t)s1 * H_ + h);
        r.x += w1 * v.x; r.y += w1 * v.y; r.z += w1 * v.z; r.w += w1 * v.w;
    }
    *(float4*)(out + (size_t)t * H_ + h) = r;
}

// ---------------- launch ----------------------------------------------------
extern "C" void kernel_launch(void* const* d_in, const int* in_sizes, int n_in,
                              void* d_out, int out_size) {
    const float* x      = (const float*)d_in[0];
    const float* logits = (const float*)d_in[1];
    const float* w13    = (const float*)d_in[2];
    const float* w2     = (const float*)d_in[3];
    float* out          = (float*)d_out;

    static int smem_set = 0;
    if (!smem_set) {
        cudaFuncSetAttribute(gemm1_mma, cudaFuncAttributeMaxDynamicSharedMemorySize, SMEM_TOTAL);
        cudaFuncSetAttribute(gemm2_mma, cudaFuncAttributeMaxDynamicSharedMemorySize, SMEM_TOTAL);
        smem_set = 1;
    }

    router_kernel<<<1, 512>>>(logits);
    prepass_kernel<<<dim3(E_ * (C_ / 128), 4), 256>>>(x);
    gemm1_mma<<<dim3(I_ / 64, E_ * (C_ / 128)), 384, SMEM_TOTAL>>>(w13);
    gemm2_mma<<<dim3(H_ / 128, E_ * (C_ / 128)), 384, SMEM_TOTAL>>>(w2);
    combine_kernel<<<(T_ * H_ / 4 + 255) / 256, 256>>>(out);
}